// round 12
// baseline (speedup 1.0000x reference)
#include <cuda_runtime.h>
#include <cuda_bf16.h>
#include <math.h>

#define B_   16
#define T_   2000
#define DIN  1280
#define D_   1024
#define NQ_  32
#define K_   1024
#define NCOL (B_*T_)
#define OUT_ELEMS ((size_t)B_*D_*T_)
#define IDX_OFF   OUT_ELEMS
#define COMMIT_OFF (OUT_ELEMS + (size_t)NQ_*NCOL)

__device__ float g_WinT[DIN*D_];
__device__ __nv_bfloat16 g_WoutH[D_*D_];
__device__ __nv_bfloat16 g_WoutL[D_*D_];
__device__ float g_WoutF[D_*D_];
__device__ float g_qin2 [NQ_*8*D_];     // pair-interleaved [q][d/2][i][2]
__device__ float g_qout2[NQ_*D_*8];     // pair-interleaved [(o,o+8) pairs][d][2]
__device__ float g_qoutF[NQ_*D_*8];     // plain [q][o][d]
__device__ float g_cbn [NQ_*K_];
__device__ float g_zp  [(size_t)B_*D_*T_];
__device__ __align__(16) __nv_bfloat16 g_qTH[(size_t)B_*T_*D_];
__device__ __align__(16) __nv_bfloat16 g_qTL[(size_t)B_*T_*D_];
__device__ int   g_selm[NQ_];
__device__ float g_csm [NQ_];
__device__ float g_S   [D_];
__device__ float g_outS[D_];
__device__ __align__(16) __nv_bfloat16 g_SH[D_];
__device__ __align__(16) __nv_bfloat16 g_SL[D_];
__device__ float g_commit[NQ_*B_];

#define CP16Z(dst, src, p) asm volatile("cp.async.cg.shared.global [%0], [%1], 16, %2;\n" :: "r"(dst), "l"(src), "r"(p))
#define CP_COMMIT() asm volatile("cp.async.commit_group;\n")
#define CP_WAIT1() asm volatile("cp.async.wait_group 1;\n")
#define CP_WAIT0() asm volatile("cp.async.wait_group 0;\n")

#define MMA_BF16(d, a0,a1,a2,a3, b0,b1) \
    asm volatile("mma.sync.aligned.m16n8k16.row.col.f32.bf16.bf16.f32 " \
        "{%0,%1,%2,%3},{%4,%5,%6,%7},{%8,%9},{%0,%1,%2,%3};\n" \
        : "+f"(d[0]),"+f"(d[1]),"+f"(d[2]),"+f"(d[3]) \
        : "r"(a0),"r"(a1),"r"(a2),"r"(a3),"r"(b0),"r"(b1))

#define PACK2(o, lo, hi) \
    asm("mov.b64 %0, {%1, %2};" : "=l"(o) : "r"(__float_as_uint(lo)), "r"(__float_as_uint(hi)))
#define FMA2(acc, a, b) \
    asm("fma.rn.f32x2 %0, %1, %2, %0;" : "+l"(acc) : "l"(a), "l"(b))
#define UNPACK2(lo, hi, in) \
    asm("mov.b64 {%0, %1}, %2;" : "=r"(lo), "=r"(hi) : "l"(in))

// ---------------- fused prep: all weight-norm / packing / constants --------
__global__ void prep_all(const float* __restrict__ in_v,  const float* __restrict__ in_g,
                         const float* __restrict__ out_v, const float* __restrict__ out_g,
                         const float* __restrict__ qi_v,  const float* __restrict__ qi_g,
                         const float* __restrict__ qo_v,  const float* __restrict__ qo_g,
                         const float* __restrict__ cb) {
    int blk = blockIdx.x, t = threadIdx.x;
    if (blk < 1024) {                     // WinT: norm + transpose
        int row = blk;
        const float* vr = in_v + (size_t)row * DIN;
        float s = 0.f;
        for (int i = t; i < DIN; i += 32) { float x = vr[i]; s = fmaf(x,x,s); }
        #pragma unroll
        for (int o = 16; o; o >>= 1) s += __shfl_xor_sync(0xffffffffu, s, o);
        float sc = in_g[row] / sqrtf(s);
        for (int i = t; i < DIN; i += 32) g_WinT[(size_t)i*D_ + row] = vr[i] * sc;
    } else if (blk < 2048) {              // Wout: F + H + L
        int row = blk - 1024;
        const float* vr = out_v + (size_t)row * D_;
        float s = 0.f;
        for (int i = t; i < D_; i += 32) { float x = vr[i]; s = fmaf(x,x,s); }
        #pragma unroll
        for (int o = 16; o; o >>= 1) s += __shfl_xor_sync(0xffffffffu, s, o);
        float sc = out_g[row] / sqrtf(s);
        for (int i = t; i < D_; i += 32) {
            float w = vr[i] * sc;
            g_WoutF[(size_t)row*D_ + i] = w;
            __nv_bfloat16 h = __float2bfloat16(w);
            g_WoutH[(size_t)row*D_ + i] = h;
            g_WoutL[(size_t)row*D_ + i] = __float2bfloat16(w - __bfloat162float(h));
        }
    } else if (blk < 2304) {              // qin pack (pair-interleaved)
        int row = blk - 2048; int q = row >> 3, d = row & 7;
        const float* vr = qi_v + (size_t)row * D_;
        float s = 0.f;
        for (int i = t; i < D_; i += 32) { float x = vr[i]; s = fmaf(x,x,s); }
        #pragma unroll
        for (int o = 16; o; o >>= 1) s += __shfl_xor_sync(0xffffffffu, s, o);
        float sc = qi_g[row] / sqrtf(s);
        float* ob = g_qin2 + q*8192 + (d>>1)*2048 + (d&1);
        for (int i = t; i < D_; i += 32) ob[i*2] = vr[i] * sc;
    } else if (blk < 3328) {              // qout norm (bitwise = old shfl tree) + pack
        int row = (blk - 2304)*32 + t;    // q*1024 + o
        int q = row >> 10, o = row & 1023;
        const float* vr = qo_v + (size_t)row * 8;
        float x0=vr[0]*vr[0], x1=vr[1]*vr[1], x2=vr[2]*vr[2], x3=vr[3]*vr[3];
        float x4=vr[4]*vr[4], x5=vr[5]*vr[5], x6=vr[6]*vr[6], x7=vr[7]*vr[7];
        float s = ((x0+x4)+(x2+x6)) + ((x1+x5)+(x3+x7));
        float sc = qo_g[row] / sqrtf(s);
        float* pf = g_qoutF + (size_t)row * 8;
        float* pp = g_qout2 + q*8192 + ((o>>4)*8 + (o&7))*16 + ((o>>3)&1);
        #pragma unroll
        for (int d = 0; d < 8; d++) { float w = vr[d]*sc; pf[d] = w; pp[d*2] = w; }
    } else if (blk < 4352) {              // cbn
        int i = (blk - 3328)*32 + t;
        const float* c = cb + (size_t)i * 8;
        float s = 0.f;
        #pragma unroll
        for (int d = 0; d < 8; d++) s = fmaf(c[d], c[d], s);
        g_cbn[i] = s;
    } else {                              // zero commit
        int i = (blk - 4352)*32 + t;
        if (i < NQ_*B_) g_commit[i] = 0.f;
    }
}

// ---------------- masked-column constants: selm, csm, S, SH/SL -------------
__global__ void masked_pre(const float* __restrict__ qinb,
                           const float* __restrict__ qoutb,
                           const float* __restrict__ cbg) {
    __shared__ float S[D_];
    __shared__ float rv[256];
    __shared__ int   ri[256];
    __shared__ int   s_sel;
    int tid = threadIdx.x;
    for (int i = tid; i < D_; i += 256) S[i] = 0.f;
    for (int q = 0; q < NQ_; q++) {
        float ze[8];
        #pragma unroll
        for (int d = 0; d < 8; d++) ze[d] = qinb[(q<<3)+d];
        float zsq = 0.f;
        #pragma unroll
        for (int d = 0; d < 8; d++) zsq += ze[d]*ze[d];
        const float* cbq = cbg + (size_t)q*8192;
        float best = 3.402823466e38f; int bk = 0;
        #pragma unroll
        for (int kk = 0; kk < 4; kk++) {
            int k = tid*4 + kk;
            const float* c = cbq + k*8;
            float dot = 0.f;
            #pragma unroll
            for (int d = 0; d < 8; d++) dot += ze[d]*c[d];
            float d2 = zsq - 2.f*dot + g_cbn[q*K_ + k];
            if (d2 < best) { best = d2; bk = k; }
        }
        rv[tid] = best; ri[tid] = bk;
        __syncthreads();
        if (tid == 0) {
            float b = rv[0]; int s = ri[0];
            for (int i = 1; i < 256; i++) if (rv[i] < b) { b = rv[i]; s = ri[i]; }
            s_sel = s;
            g_selm[q] = s;
            const float* c = cbq + s*8;
            float cs = 0.f;
            #pragma unroll
            for (int d = 0; d < 8; d++) { float dz = ze[d]-c[d]; cs = fmaf(dz,dz,cs); }
            g_csm[q] = cs;
        }
        __syncthreads();
        int sel = s_sel;
        const float* c = cbq + sel*8;
        float c0=c[0],c1=c[1],c2=c[2],c3=c[3],c4=c[4],c5=c[5],c6=c[6],c7=c[7];
        for (int o = tid; o < D_; o += 256) {
            const float* w = g_qoutF + ((size_t)q*D_ + o)*8;
            float v = qoutb[(q<<10)+o];
            v = fmaf(w[0],c0,v); v = fmaf(w[1],c1,v);
            v = fmaf(w[2],c2,v); v = fmaf(w[3],c3,v);
            v = fmaf(w[4],c4,v); v = fmaf(w[5],c5,v);
            v = fmaf(w[6],c6,v); v = fmaf(w[7],c7,v);
            S[o] += v;
        }
        __syncthreads();
    }
    for (int i = tid; i < D_; i += 256) {
        float v = S[i];
        g_S[i] = v;
        __nv_bfloat16 h = __float2bfloat16(v);
        g_SH[i] = h;
        g_SL[i] = __float2bfloat16(v - __bfloat162float(h));
    }
}

__global__ void commit_fin(float* __restrict__ dout) {
    if (threadIdx.x < NQ_*B_)
        dout[COMMIT_OFF + threadIdx.x] = g_commit[threadIdx.x] * (1.0f / (float)(T_*8));
}

// masked-output vector (batch-independent): outS[o] = WoutF[o]·S + bias[o]
__global__ void gemv_S(const float* __restrict__ bias) {
    int o = blockIdx.x;
    const float* w = g_WoutF + (size_t)o * D_;
    float acc = 0.f;
    for (int i = threadIdx.x; i < D_; i += 32) acc = fmaf(w[i], g_S[i], acc);
    #pragma unroll
    for (int off = 16; off; off >>= 1) acc += __shfl_xor_sync(0xffffffffu, acc, off);
    if (threadIdx.x == 0) g_outS[o] = acc + bias[o];
}

// ---- fp32 SGEMM, 128x256 tile, 8x16/thread, FFMA2, cp.async double-buffer --
__global__ __launch_bounds__(256, 1) void sgemm256(
    const float* __restrict__ AT, const float* __restrict__ B0,
    const float* __restrict__ bias, float* __restrict__ C0,
    const int* __restrict__ lens,
    int N, int Kd, int Mtot, size_t strideB, size_t strideC)
{
    extern __shared__ float smem[];
    const float* Bm = B0 + (size_t)blockIdx.z * strideB;
    float* Cm = C0 + (size_t)blockIdx.z * strideC;
    int bm = blockIdx.y << 7, bn = blockIdx.x << 8;
    int tid = threadIdx.x;

    if (bn >= lens[blockIdx.z]) {
        float4 zz = make_float4(0.f,0.f,0.f,0.f);
        #pragma unroll
        for (int u = 0; u < 32; u++) {
            int i = tid + u*256;
            int r = i >> 6, c4 = (i & 63) * 4;
            int col = bn + c4;
            if (col < N) *(float4*)&Cm[(size_t)(bm + r) * N + col] = zz;
        }
        return;
    }

    int tx = tid & 15, ty = tid >> 4;

    unsigned long long acc2[8][8];
    #pragma unroll
    for (int i = 0; i < 8; i++)
        #pragma unroll
        for (int j = 0; j < 8; j++) acc2[i][j] = 0ULL;

    auto load_tile = [&](int k0, int buf) {
        float* As = smem + buf * 6144;
        float* Bs = As + 2048;
        #pragma unroll
        for (int u = 0; u < 2; u++) {
            int i = tid + u*256;
            int r = i >> 5, c = (i & 31) * 4;
            unsigned d = (unsigned)__cvta_generic_to_shared(As + r*128 + c);
            CP16Z(d, AT + (size_t)(k0 + r)*Mtot + bm + c, 16);
        }
        #pragma unroll
        for (int u = 0; u < 4; u++) {
            int i = tid + u*256;
            int r = i >> 6, c = (i & 63) * 4;
            int col = bn + c;
            int p = 16;
            if (col >= N) { col = 0; p = 0; }
            unsigned d = (unsigned)__cvta_generic_to_shared(Bs + r*256 + c);
            CP16Z(d, Bm + (size_t)(k0 + r)*N + col, p);
        }
        CP_COMMIT();
    };

    int ntiles = Kd >> 4;
    load_tile(0, 0);
    for (int ti = 0; ti < ntiles; ti++) {
        if (ti > 0) __syncthreads();
        if (ti + 1 < ntiles) { load_tile((ti+1) << 4, (ti+1)&1); CP_WAIT1(); }
        else CP_WAIT0();
        __syncthreads();
        const float* As = smem + (ti&1) * 6144;
        const float* Bs = As + 2048;
        #pragma unroll
        for (int kk = 0; kk < 16; kk++) {
            float af[8], bf[16];
            *(float4*)&af[0] = *(const float4*)&As[kk*128 + ty*8];
            *(float4*)&af[4] = *(const float4*)&As[kk*128 + ty*8 + 4];
            #pragma unroll
            for (int c = 0; c < 4; c++)
                *(float4*)&bf[c*4] = *(const float4*)&Bs[kk*256 + c*64 + tx*4];
            unsigned long long bb[8];
            #pragma unroll
            for (int j = 0; j < 8; j++) PACK2(bb[j], bf[2*j], bf[2*j+1]);
            #pragma unroll
            for (int i = 0; i < 8; i++) {
                unsigned long long aa;
                PACK2(aa, af[i], af[i]);
                #pragma unroll
                for (int j = 0; j < 8; j++) FMA2(acc2[i][j], aa, bb[j]);
            }
        }
    }
    #pragma unroll
    for (int i = 0; i < 8; i++) {
        int row = bm + ty*8 + i;
        float bv = bias[row];
        #pragma unroll
        for (int c = 0; c < 4; c++) {
            int col = bn + c*64 + tx*4;
            if (col < N) {
                unsigned l0, h0, l1, h1;
                UNPACK2(l0, h0, acc2[i][2*c]);
                UNPACK2(l1, h1, acc2[i][2*c+1]);
                float4 o;
                o.x = __uint_as_float(l0) + bv;
                o.y = __uint_as_float(h0) + bv;
                o.z = __uint_as_float(l1) + bv;
                o.w = __uint_as_float(h1) + bv;
                *(float4*)&Cm[(size_t)row * N + col] = o;
            }
        }
    }
}

// ------- bf16x2-split GEMM (3 products) + masked-block broadcast ------------
__global__ __launch_bounds__(256, 1) void gemm_bf16x2(
    const __nv_bfloat16* __restrict__ AH, const __nv_bfloat16* __restrict__ AL,
    const __nv_bfloat16* __restrict__ BH0, const __nv_bfloat16* __restrict__ BL0,
    const float* __restrict__ bias, float* __restrict__ C0,
    const int* __restrict__ lens,
    int N, int Kd, size_t sB, size_t sC)
{
    extern __shared__ __align__(16) unsigned char sb[];
    const __nv_bfloat16* BH = BH0 + (size_t)blockIdx.z * sB;
    const __nv_bfloat16* BL = BL0 + (size_t)blockIdx.z * sB;
    float* Cm = C0 + (size_t)blockIdx.z * sC;
    int bm = blockIdx.y << 7, bn = blockIdx.x << 7;
    int tid = threadIdx.x, lane = tid & 31, wid = tid >> 5;

    if (bn >= lens[blockIdx.z]) {
        const float* oS = g_outS + bm;
        #pragma unroll
        for (int u = 0; u < 16; u++) {
            int i = tid + u*256;
            int r = i >> 5, c4 = (i & 31) * 4;
            int col = bn + c4;
            float v = oS[r];
            if (col < N) *(float4*)&Cm[(size_t)(bm + r) * N + col] = make_float4(v,v,v,v);
        }
        return;
    }

    int wm = (wid & 3) << 5, wn = (wid >> 2) << 6;
    int lq = lane >> 2, lr = lane & 3;
    int ntiles = Kd >> 5;

    float acc[2][8][4];
    #pragma unroll
    for (int mi = 0; mi < 2; mi++)
        #pragma unroll
        for (int ni = 0; ni < 8; ni++)
            #pragma unroll
            for (int c = 0; c < 4; c++) acc[mi][ni][c] = 0.f;

    auto load_tile = [&](int ti, int buf) {
        unsigned char* base = sb + buf * 40960;
        int k0 = ti << 5;
        #pragma unroll
        for (int r = 0; r < 8; r++) {
            int idx = r*256 + tid;
            int region = idx >> 9, w = idx & 511;
            int row = w >> 2, ch = w & 3;
            unsigned daddr = (unsigned)__cvta_generic_to_shared(base + region*10240 + row*80 + ch*16);
            const __nv_bfloat16* src; int p = 16;
            if (region == 0)      src = AH + (size_t)(bm+row)*Kd + k0 + ch*8;
            else if (region == 1) src = AL + (size_t)(bm+row)*Kd + k0 + ch*8;
            else {
                int gr = bn + row; if (gr >= N) { gr = 0; p = 0; }
                src = (region == 2 ? BH : BL) + (size_t)gr*Kd + k0 + ch*8;
            }
            CP16Z(daddr, src, p);
        }
        CP_COMMIT();
    };

    load_tile(0, 0);
    for (int ti = 0; ti < ntiles; ti++) {
        if (ti > 0) __syncthreads();
        if (ti + 1 < ntiles) { load_tile(ti+1, (ti+1)&1); CP_WAIT1(); }
        else CP_WAIT0();
        __syncthreads();
        const unsigned char* base = sb + (ti&1) * 40960;
        const unsigned char* AsH = base;
        const unsigned char* AsL = base + 10240;
        const unsigned char* BsH = base + 20480;
        const unsigned char* BsL = base + 30720;
        #pragma unroll
        for (int ks = 0; ks < 2; ks++) {
            int kb = ks*32 + lr*4;
            unsigned aH[2][4], aL[2][4], bH[8][2], bL[8][2];
            #pragma unroll
            for (int mi = 0; mi < 2; mi++) {
                int off = (wm + (mi<<4) + lq)*80 + kb;
                aH[mi][0] = *(const unsigned*)(AsH + off);
                aH[mi][1] = *(const unsigned*)(AsH + off + 8*80);
                aH[mi][2] = *(const unsigned*)(AsH + off + 16);
                aH[mi][3] = *(const unsigned*)(AsH + off + 8*80 + 16);
                aL[mi][0] = *(const unsigned*)(AsL + off);
                aL[mi][1] = *(const unsigned*)(AsL + off + 8*80);
                aL[mi][2] = *(const unsigned*)(AsL + off + 16);
                aL[mi][3] = *(const unsigned*)(AsL + off + 8*80 + 16);
            }
            #pragma unroll
            for (int ni = 0; ni < 8; ni++) {
                int off = (wn + (ni<<3) + lq)*80 + kb;
                bH[ni][0] = *(const unsigned*)(BsH + off);
                bH[ni][1] = *(const unsigned*)(BsH + off + 16);
                bL[ni][0] = *(const unsigned*)(BsL + off);
                bL[ni][1] = *(const unsigned*)(BsL + off + 16);
            }
            #pragma unroll
            for (int mi = 0; mi < 2; mi++)
                #pragma unroll
                for (int ni = 0; ni < 8; ni++) {
                    MMA_BF16(acc[mi][ni], aH[mi][0],aH[mi][1],aH[mi][2],aH[mi][3], bH[ni][0],bH[ni][1]);
                    MMA_BF16(acc[mi][ni], aH[mi][0],aH[mi][1],aH[mi][2],aH[mi][3], bL[ni][0],bL[ni][1]);
                    MMA_BF16(acc[mi][ni], aL[mi][0],aL[mi][1],aL[mi][2],aL[mi][3], bH[ni][0],bH[ni][1]);
                }
        }
    }
    #pragma unroll
    for (int mi = 0; mi < 2; mi++) {
        int row0 = bm + wm + (mi<<4) + lq;
        float b0 = bias[row0], b1 = bias[row0 + 8];
        #pragma unroll
        for (int ni = 0; ni < 8; ni++) {
            int col = bn + wn + (ni<<3) + (lr<<1);
            if (col < N) {
                float2 v0 = make_float2(acc[mi][ni][0] + b0, acc[mi][ni][1] + b0);
                float2 v1 = make_float2(acc[mi][ni][2] + b1, acc[mi][ni][3] + b1);
                *(float2*)&Cm[(size_t)row0 * N + col] = v0;
                *(float2*)&Cm[(size_t)(row0+8) * N + col] = v1;
            }
        }
    }
}

// ---------------- fused 32-round RVQ scan: 1 CTA = 32 columns ----------------
__global__ __launch_bounds__(256, 1) void rvq_scan(
    const int*   __restrict__ lens,
    const float* __restrict__ cbg,
    const float* __restrict__ qinb,
    const float* __restrict__ qoutb,
    float*       __restrict__ dout)
{
    extern __shared__ float sm[];
    float* s_res = sm;                 // 33792
    float* s_w   = s_res + 33792;      // 8192 (qin2 / qout2 packed)
    float* s_cb  = s_w + 8192;         // 8192
    float* s_cbn = s_cb + 8192;        // 1024
    float* s_red = s_cbn + 1024;       // 2048
    float* s_ze  = s_red + 2048;       // 256
    float* s_ob  = s_ze + 256;         // 1024
    float* s_mk  = s_ob + 1024;        // 32
    int*   s_sel = (int*)(s_mk + 32);
    int*   s_bi  = s_sel + 32;
    int*   s_ti  = s_bi + 32;
    int*   s_fl  = s_ti + 32;

    const int tid = threadIdx.x;
    const int lane = tid & 31, wrp = tid >> 5;
    const int c0 = blockIdx.x << 5;

    if (tid < 32) {
        int c = c0 + tid;
        int b = c / T_, t = c - b * T_;
        s_bi[tid] = b; s_ti[tid] = t;
        s_mk[tid] = (t < lens[b]) ? 1.f : 0.f;
    }
    __syncthreads();
    if (tid == 0) {
        float m = 0.f;
        #pragma unroll
        for (int n = 0; n < 32; n++) m += s_mk[n];
        s_fl[0] = (m == 0.f) ? 1 : 0;
    }
    __syncthreads();

    if (s_fl[0]) {
        // ---- fully-masked CTA: constants precomputed, just write outputs ----
        unsigned* sSH = (unsigned*)s_res;         // 512 u32
        unsigned* sSL = sSH + 512;                // 512 u32
        for (int i = tid; i < 512; i += 256) {
            sSH[i] = ((const unsigned*)g_SH)[i];
            sSL[i] = ((const unsigned*)g_SL)[i];
        }
        for (int q = wrp; q < NQ_; q += 8) {
            dout[IDX_OFF + (size_t)q*NCOL + c0 + lane] = (float)g_selm[q];
            atomicAdd(&g_commit[(q<<4) + s_bi[lane]], g_csm[q]);
        }
        __syncthreads();
        for (int i = tid; i < 32*128; i += 256) {
            int n = i >> 7, j = i & 127;
            size_t base = ((size_t)s_bi[n]*T_ + s_ti[n])*D_;
            ((uint4*)(g_qTH + base))[j] = ((const uint4*)sSH)[j];
            ((uint4*)(g_qTL + base))[j] = ((const uint4*)sSL)[j];
        }
        return;
    }

    for (int idx = tid; idx < D_*32; idx += 256) {
        int o = idx >> 5, n = idx & 31;
        s_res[o*33+n] = g_zp[(size_t)s_bi[n]*(D_*T_) + (size_t)o*T_ + s_ti[n]];
    }

    for (int q = 0; q < NQ_; q++) {
        {
            const float4* gc = (const float4*)(cbg + (size_t)q*8192);
            const float4* gq = (const float4*)(g_qin2 + q*8192);
            #pragma unroll
            for (int u = 0; u < 8; u++) {
                ((float4*)s_w)[tid + u*256]  = gq[tid + u*256];
                ((float4*)s_cb)[tid + u*256] = gc[tid + u*256];
            }
            #pragma unroll
            for (int u = 0; u < 4; u++) s_cbn[tid + u*256] = g_cbn[q*K_ + tid + u*256];
        }
        __syncthreads();

        { // phase B: ze partials via FFMA2 (bit-identical chain)
            unsigned long long part2[4];
            #pragma unroll
            for (int j = 0; j < 4; j++) part2[j] = 0ULL;
            int ib = wrp << 7;
            for (int ii = 0; ii < 128; ii += 4) {
                float r0 = s_res[(ib+ii+0)*33+lane];
                float r1 = s_res[(ib+ii+1)*33+lane];
                float r2 = s_res[(ib+ii+2)*33+lane];
                float r3 = s_res[(ib+ii+3)*33+lane];
                unsigned long long rr0, rr1, rr2, rr3;
                PACK2(rr0, r0, r0); PACK2(rr1, r1, r1);
                PACK2(rr2, r2, r2); PACK2(rr3, r3, r3);
                #pragma unroll
                for (int j = 0; j < 4; j++) {
                    const ulonglong2* qp = (const ulonglong2*)&s_w[j*2048 + ((ib+ii)<<1)];
                    ulonglong2 qA = qp[0];
                    ulonglong2 qB = qp[1];
                    FMA2(part2[j], qB.y, rr3);
                    FMA2(part2[j], qB.x, rr2);
                    FMA2(part2[j], qA.y, rr1);
                    FMA2(part2[j], qA.x, rr0);
                }
            }
            #pragma unroll
            for (int j = 0; j < 4; j++) {
                unsigned lo, hi;
                UNPACK2(lo, hi, part2[j]);
                s_red[(wrp<<8)+(lane<<3)+2*j]   = __uint_as_float(lo);
                s_red[(wrp<<8)+(lane<<3)+2*j+1] = __uint_as_float(hi);
            }
        }
        __syncthreads();
        {
            int d = tid >> 5, n = tid & 31;
            float s = 0.f;
            #pragma unroll
            for (int w2 = 0; w2 < 8; w2++) s += s_red[(w2<<8)+(n<<3)+d];
            s_ze[(n<<3)+d] = s_mk[n]*s + qinb[(q<<3)+d];
        }
        __syncthreads();

        { // phase C: per-warp argmin (unchanged)
            float4 za = *(float4*)&s_ze[lane<<3];
            float4 zb = *(float4*)&s_ze[(lane<<3)+4];
            float zsq = za.x*za.x+za.y*za.y+za.z*za.z+za.w*za.w
                      + zb.x*zb.x+zb.y*zb.y+zb.z*zb.z+zb.w*zb.w;
            float best = 3.402823466e38f; int bk = 0;
            int kb = wrp << 7;
            #pragma unroll 4
            for (int kk = 0; kk < 128; kk++) {
                int k = kb + kk;
                float4 ca = *(float4*)&s_cb[k<<3];
                float4 cv = *(float4*)&s_cb[(k<<3)+4];
                float dot = za.x*ca.x+za.y*ca.y+za.z*ca.z+za.w*ca.w
                          + zb.x*cv.x+zb.y*cv.y+zb.z*cv.z+zb.w*cv.w;
                float d2 = zsq - 2.f*dot + s_cbn[k];
                if (d2 < best) { best = d2; bk = k; }
            }
            s_red[(wrp<<6)+(lane<<1)]   = best;
            s_red[(wrp<<6)+(lane<<1)+1] = __int_as_float(bk);
        }
        __syncthreads();

        if (wrp == 0) { // phase D + commit
            int n = lane;
            float best = s_red[n<<1]; int bk = __float_as_int(s_red[(n<<1)+1]);
            #pragma unroll
            for (int w2 = 1; w2 < 8; w2++) {
                float v = s_red[(w2<<6)+(n<<1)];
                if (v < best) { best = v; bk = __float_as_int(s_red[(w2<<6)+(n<<1)+1]); }
            }
            s_sel[n] = bk;
            dout[IDX_OFF + (size_t)q*NCOL + c0 + n] = (float)bk;
            float cs = 0.f;
            #pragma unroll
            for (int d = 0; d < 8; d++) {
                float dz = s_ze[(n<<3)+d] - s_cb[(bk<<3)+d];
                cs = fmaf(dz, dz, cs);
            }
            atomicAdd(&g_commit[(q<<4) + s_bi[n]], cs);
        } else {       // stage qout2 (packed) + ob
            int t2 = tid - 32;
            const float4* gw = (const float4*)(g_qout2 + q*8192);
            for (int i = t2; i < 2048; i += 224) ((float4*)s_w)[i] = gw[i];
            for (int i = t2; i < 1024; i += 224) s_ob[i] = qoutb[(q<<10) + i];
        }
        __syncthreads();

        { // phase E: res -= Wq_out@cb[sel] + ob, FFMA2 over (o,o+8) pairs
            int n = tid & 31;
            int ob = tid >> 5;
            int sel = s_sel[n];
            float4 ca = *(float4*)&s_cb[sel<<3];
            float4 cv = *(float4*)&s_cb[(sel<<3)+4];
            unsigned long long cc[8];
            PACK2(cc[0], ca.x, ca.x); PACK2(cc[1], ca.y, ca.y);
            PACK2(cc[2], ca.z, ca.z); PACK2(cc[3], ca.w, ca.w);
            PACK2(cc[4], cv.x, cv.x); PACK2(cc[5], cv.y, cv.y);
            PACK2(cc[6], cv.z, cv.z); PACK2(cc[7], cv.w, cv.w);
            #pragma unroll 4
            for (int m = 0; m < 64; m++) {
                const float* wp = &s_w[(m*8 + ob)*16];
                ulonglong2 w01 = *(const ulonglong2*)(wp);
                ulonglong2 w23 = *(const ulonglong2*)(wp + 4);
                ulonglong2 w45 = *(const ulonglong2*)(wp + 8);
                ulonglong2 w67 = *(const ulonglong2*)(wp + 12);
                int o = (m << 4) + ob;
                unsigned long long v2;
                PACK2(v2, s_ob[o], s_ob[o+8]);
                FMA2(v2, w01.x, cc[0]); FMA2(v2, w01.y, cc[1]);
                FMA2(v2, w23.x, cc[2]); FMA2(v2, w23.y, cc[3]);
                FMA2(v2, w45.x, cc[4]); FMA2(v2, w45.y, cc[5]);
                FMA2(v2, w67.x, cc[6]); FMA2(v2, w67.y, cc[7]);
                unsigned lo, hi;
                UNPACK2(lo, hi, v2);
                s_res[o*33+n]     -= __uint_as_float(lo);
                s_res[(o+8)*33+n] -= __uint_as_float(hi);
            }
        }
        __syncthreads();
    }

    // q = zp - res; write transposed bf16 hi/lo [b][t][o]
    for (int idx = tid; idx < D_*32; idx += 256) {
        int o = idx >> 5, n = idx & 31;
        size_t ga = (size_t)s_bi[n]*(D_*T_) + (size_t)o*T_ + s_ti[n];
        s_res[o*33+n] = g_zp[ga] - s_res[o*33+n];
    }
    __syncthreads();
    for (int idx = tid; idx < D_*32; idx += 256) {
        int n = idx >> 10, o = idx & 1023;
        float v = s_res[o*33+n];
        __nv_bfloat16 h = __float2bfloat16(v);
        size_t a = ((size_t)s_bi[n]*T_ + s_ti[n])*D_ + o;
        g_qTH[a] = h;
        g_qTL[a] = __float2bfloat16(v - __bfloat162float(h));
    }
}

extern "C" void kernel_launch(void* const* d_in, const int* in_sizes, int n_in,
                              void* d_out, int out_size) {
    const float* z          = (const float*)d_in[0];
    const int*   lens       = (const int*)d_in[1];
    const float* in_proj_v  = (const float*)d_in[2];
    const float* in_proj_g  = (const float*)d_in[3];
    const float* in_proj_b  = (const float*)d_in[4];
    const float* out_proj_v = (const float*)d_in[5];
    const float* out_proj_g = (const float*)d_in[6];
    const float* out_proj_b = (const float*)d_in[7];
    const float* q_in_v     = (const float*)d_in[8];
    const float* q_in_g     = (const float*)d_in[9];
    const float* q_in_b     = (const float*)d_in[10];
    const float* q_out_v    = (const float*)d_in[11];
    const float* q_out_g    = (const float*)d_in[12];
    const float* q_out_b    = (const float*)d_in[13];
    const float* codebooks  = (const float*)d_in[14];
    float* dout = (float*)d_out;

    void *pWinT, *pWoutH, *pWoutL, *pzp, *pqTH, *pqTL;
    cudaGetSymbolAddress(&pWinT,  g_WinT);
    cudaGetSymbolAddress(&pWoutH, g_WoutH);
    cudaGetSymbolAddress(&pWoutL, g_WoutL);
    cudaGetSymbolAddress(&pzp,    g_zp);
    cudaGetSymbolAddress(&pqTH,   g_qTH);
    cudaGetSymbolAddress(&pqTL,   g_qTL);

    cudaFuncSetAttribute(rvq_scan,   cudaFuncAttributeMaxDynamicSharedMemorySize, 218656);
    cudaFuncSetAttribute(gemm_bf16x2, cudaFuncAttributeMaxDynamicSharedMemorySize, 81920);
    cudaFuncSetAttribute(sgemm256,   cudaFuncAttributeMaxDynamicSharedMemorySize, 49152);

    // launch order: rvq_scan is the 4th launch -> ncu capture lands on it
    prep_all<<<4368, 32>>>(in_proj_v, in_proj_g, out_proj_v, out_proj_g,
                           q_in_v, q_in_g, q_out_v, q_out_g, codebooks);
    masked_pre<<<1, 256>>>(q_in_b, q_out_b, codebooks);

    sgemm256<<<dim3((T_+255)/256, D_/128, B_), 256, 49152>>>(
        (const float*)pWinT, z, in_proj_b, (float*)pzp, lens,
        T_, DIN, D_, (size_t)DIN*T_, (size_t)D_*T_);

    rvq_scan<<<NCOL/32, 256, 218656>>>(lens, codebooks, q_in_b, q_out_b, dout);

    gemv_S<<<D_, 32>>>(out_proj_b);
    commit_fin<<<1, 512>>>(dout);

    gemm_bf16x2<<<dim3((T_+127)/128, D_/128, B_), 256, 81920>>>(
        (const __nv_bfloat16*)pWoutH, (const __nv_bfloat16*)pWoutL,
        (const __nv_bfloat16*)pqTH, (const __nv_bfloat16*)pqTL,
        out_proj_b, dout, lens, T_, D_, (size_t)T_*D_, (size_t)D_*T_);
}

// round 13
// speedup vs baseline: 1.1239x; 1.1239x over previous
#include <cuda_runtime.h>
#include <cuda_bf16.h>
#include <math.h>

#define B_   16
#define T_   2000
#define DIN  1280
#define D_   1024
#define NQ_  32
#define K_   1024
#define NCOL (B_*T_)
#define OUT_ELEMS ((size_t)B_*D_*T_)
#define IDX_OFF   OUT_ELEMS
#define COMMIT_OFF (OUT_ELEMS + (size_t)NQ_*NCOL)

__device__ float g_WinT[DIN*D_];
__device__ __nv_bfloat16 g_WoutH[D_*D_];
__device__ __nv_bfloat16 g_WoutL[D_*D_];
__device__ float g_WoutF[D_*D_];
__device__ float g_qin2 [NQ_*8*D_];
__device__ float g_qout2[NQ_*D_*8];
__device__ float g_qoutF[NQ_*D_*8];
__device__ float g_cbn [NQ_*K_];
__device__ float g_zp  [(size_t)B_*D_*T_];
__device__ __align__(16) __nv_bfloat16 g_qTH[(size_t)B_*T_*D_];
__device__ __align__(16) __nv_bfloat16 g_qTL[(size_t)B_*T_*D_];
__device__ int   g_selm[NQ_];
__device__ float g_csm [NQ_];
__device__ float g_S   [D_];
__device__ float g_outS[D_];
__device__ __align__(16) __nv_bfloat16 g_SH[D_];
__device__ __align__(16) __nv_bfloat16 g_SL[D_];
__device__ float g_commit[NQ_*B_];

#define CP16Z(dst, src, p) asm volatile("cp.async.cg.shared.global [%0], [%1], 16, %2;\n" :: "r"(dst), "l"(src), "r"(p))
#define CP_COMMIT() asm volatile("cp.async.commit_group;\n")
#define CP_WAIT1() asm volatile("cp.async.wait_group 1;\n")
#define CP_WAIT0() asm volatile("cp.async.wait_group 0;\n")

#define MMA_BF16(d, a0,a1,a2,a3, b0,b1) \
    asm volatile("mma.sync.aligned.m16n8k16.row.col.f32.bf16.bf16.f32 " \
        "{%0,%1,%2,%3},{%4,%5,%6,%7},{%8,%9},{%0,%1,%2,%3};\n" \
        : "+f"(d[0]),"+f"(d[1]),"+f"(d[2]),"+f"(d[3]) \
        : "r"(a0),"r"(a1),"r"(a2),"r"(a3),"r"(b0),"r"(b1))

#define PACK2(o, lo, hi) \
    asm("mov.b64 %0, {%1, %2};" : "=l"(o) : "r"(__float_as_uint(lo)), "r"(__float_as_uint(hi)))
#define FMA2(acc, a, b) \
    asm("fma.rn.f32x2 %0, %1, %2, %0;" : "+l"(acc) : "l"(a), "l"(b))
#define UNPACK2(lo, hi, in) \
    asm("mov.b64 {%0, %1}, %2;" : "=r"(lo), "=r"(hi) : "l"(in))

// ---------------- fused prep ------------------------------------------------
__global__ void prep_all(const float* __restrict__ in_v,  const float* __restrict__ in_g,
                         const float* __restrict__ out_v, const float* __restrict__ out_g,
                         const float* __restrict__ qi_v,  const float* __restrict__ qi_g,
                         const float* __restrict__ qo_v,  const float* __restrict__ qo_g,
                         const float* __restrict__ cb) {
    int blk = blockIdx.x, t = threadIdx.x;
    if (blk < 1024) {
        int row = blk;
        const float* vr = in_v + (size_t)row * DIN;
        float s = 0.f;
        for (int i = t; i < DIN; i += 32) { float x = vr[i]; s = fmaf(x,x,s); }
        #pragma unroll
        for (int o = 16; o; o >>= 1) s += __shfl_xor_sync(0xffffffffu, s, o);
        float sc = in_g[row] / sqrtf(s);
        for (int i = t; i < DIN; i += 32) g_WinT[(size_t)i*D_ + row] = vr[i] * sc;
    } else if (blk < 2048) {
        int row = blk - 1024;
        const float* vr = out_v + (size_t)row * D_;
        float s = 0.f;
        for (int i = t; i < D_; i += 32) { float x = vr[i]; s = fmaf(x,x,s); }
        #pragma unroll
        for (int o = 16; o; o >>= 1) s += __shfl_xor_sync(0xffffffffu, s, o);
        float sc = out_g[row] / sqrtf(s);
        for (int i = t; i < D_; i += 32) {
            float w = vr[i] * sc;
            g_WoutF[(size_t)row*D_ + i] = w;
            __nv_bfloat16 h = __float2bfloat16(w);
            g_WoutH[(size_t)row*D_ + i] = h;
            g_WoutL[(size_t)row*D_ + i] = __float2bfloat16(w - __bfloat162float(h));
        }
    } else if (blk < 2304) {
        int row = blk - 2048; int q = row >> 3, d = row & 7;
        const float* vr = qi_v + (size_t)row * D_;
        float s = 0.f;
        for (int i = t; i < D_; i += 32) { float x = vr[i]; s = fmaf(x,x,s); }
        #pragma unroll
        for (int o = 16; o; o >>= 1) s += __shfl_xor_sync(0xffffffffu, s, o);
        float sc = qi_g[row] / sqrtf(s);
        float* ob = g_qin2 + q*8192 + (d>>1)*2048 + (d&1);
        for (int i = t; i < D_; i += 32) ob[i*2] = vr[i] * sc;
    } else if (blk < 3328) {
        int row = (blk - 2304)*32 + t;
        int q = row >> 10, o = row & 1023;
        const float* vr = qo_v + (size_t)row * 8;
        float x0=vr[0]*vr[0], x1=vr[1]*vr[1], x2=vr[2]*vr[2], x3=vr[3]*vr[3];
        float x4=vr[4]*vr[4], x5=vr[5]*vr[5], x6=vr[6]*vr[6], x7=vr[7]*vr[7];
        float s = ((x0+x4)+(x2+x6)) + ((x1+x5)+(x3+x7));
        float sc = qo_g[row] / sqrtf(s);
        float* pf = g_qoutF + (size_t)row * 8;
        float* pp = g_qout2 + q*8192 + ((o>>4)*8 + (o&7))*16 + ((o>>3)&1);
        #pragma unroll
        for (int d = 0; d < 8; d++) { float w = vr[d]*sc; pf[d] = w; pp[d*2] = w; }
    } else if (blk < 4352) {
        int i = (blk - 3328)*32 + t;
        const float* c = cb + (size_t)i * 8;
        float s = 0.f;
        #pragma unroll
        for (int d = 0; d < 8; d++) s = fmaf(c[d], c[d], s);
        g_cbn[i] = s;
    } else {
        int i = (blk - 4352)*32 + t;
        if (i < NQ_*B_) g_commit[i] = 0.f;
    }
}

// ---- masked constants: per-q argmin (parallel, first-min preserving) -------
__global__ void masked_sel(const float* __restrict__ qinb,
                           const float* __restrict__ cbg) {
    __shared__ float sv[256];
    __shared__ int   si[256];
    int q = blockIdx.x, tid = threadIdx.x;
    float ze[8];
    #pragma unroll
    for (int d = 0; d < 8; d++) ze[d] = qinb[(q<<3)+d];
    float zsq = 0.f;
    #pragma unroll
    for (int d = 0; d < 8; d++) zsq += ze[d]*ze[d];
    const float* cbq = cbg + (size_t)q*8192;
    float best = 3.402823466e38f; int bk = 0;
    #pragma unroll
    for (int kk = 0; kk < 4; kk++) {
        int k = tid*4 + kk;
        const float* c = cbq + k*8;
        float dot = 0.f;
        #pragma unroll
        for (int d = 0; d < 8; d++) dot += ze[d]*c[d];
        float d2 = zsq - 2.f*dot + g_cbn[q*K_ + k];
        if (d2 < best) { best = d2; bk = k; }
    }
    sv[tid] = best; si[tid] = bk;
    __syncthreads();
    for (int s = 128; s; s >>= 1) {              // partner has higher k range:
        if (tid < s && sv[tid+s] < sv[tid]) { sv[tid] = sv[tid+s]; si[tid] = si[tid+s]; }
        __syncthreads();
    }
    if (tid == 0) {
        int s = si[0];
        g_selm[q] = s;
        const float* c = cbq + s*8;
        float cs = 0.f;
        #pragma unroll
        for (int d = 0; d < 8; d++) { float dz = ze[d]-c[d]; cs = fmaf(dz,dz,cs); }
        g_csm[q] = cs;
    }
}

// ---- masked S vector: q-ascending accumulation (identical chain) -----------
__global__ void masked_S(const float* __restrict__ qoutb,
                         const float* __restrict__ cbg) {
    int o = blockIdx.x * 256 + threadIdx.x;
    float acc = 0.f;
    for (int q = 0; q < NQ_; q++) {
        int sel = g_selm[q];
        const float* c = cbg + (size_t)q*8192 + sel*8;
        const float* w = g_qoutF + ((size_t)q*D_ + o)*8;
        float v = qoutb[(q<<10)+o];
        v = fmaf(w[0],c[0],v); v = fmaf(w[1],c[1],v);
        v = fmaf(w[2],c[2],v); v = fmaf(w[3],c[3],v);
        v = fmaf(w[4],c[4],v); v = fmaf(w[5],c[5],v);
        v = fmaf(w[6],c[6],v); v = fmaf(w[7],c[7],v);
        acc += v;
    }
    g_S[o] = acc;
    __nv_bfloat16 h = __float2bfloat16(acc);
    g_SH[o] = h;
    g_SL[o] = __float2bfloat16(acc - __bfloat162float(h));
}

__global__ void commit_fin(float* __restrict__ dout) {
    if (threadIdx.x < NQ_*B_)
        dout[COMMIT_OFF + threadIdx.x] = g_commit[threadIdx.x] * (1.0f / (float)(T_*8));
}

__global__ void gemv_S(const float* __restrict__ bias) {
    int o = blockIdx.x;
    const float* w = g_WoutF + (size_t)o * D_;
    float acc = 0.f;
    for (int i = threadIdx.x; i < D_; i += 32) acc = fmaf(w[i], g_S[i], acc);
    #pragma unroll
    for (int off = 16; off; off >>= 1) acc += __shfl_xor_sync(0xffffffffu, acc, off);
    if (threadIdx.x == 0) g_outS[o] = acc + bias[o];
}

// ---- fp32 SGEMM, 128x256 tile, FFMA2, cp.async double-buffer ---------------
__global__ __launch_bounds__(256, 1) void sgemm256(
    const float* __restrict__ AT, const float* __restrict__ B0,
    const float* __restrict__ bias, float* __restrict__ C0,
    const int* __restrict__ lens,
    int N, int Kd, int Mtot, size_t strideB, size_t strideC)
{
    extern __shared__ float smem[];
    const float* Bm = B0 + (size_t)blockIdx.z * strideB;
    float* Cm = C0 + (size_t)blockIdx.z * strideC;
    int bm = blockIdx.y << 7, bn = blockIdx.x << 8;
    int tid = threadIdx.x;

    if (bn >= lens[blockIdx.z]) {
        float4 zz = make_float4(0.f,0.f,0.f,0.f);
        #pragma unroll
        for (int u = 0; u < 32; u++) {
            int i = tid + u*256;
            int r = i >> 6, c4 = (i & 63) * 4;
            int col = bn + c4;
            if (col < N) *(float4*)&Cm[(size_t)(bm + r) * N + col] = zz;
        }
        return;
    }

    int tx = tid & 15, ty = tid >> 4;
    unsigned long long acc2[8][8];
    #pragma unroll
    for (int i = 0; i < 8; i++)
        #pragma unroll
        for (int j = 0; j < 8; j++) acc2[i][j] = 0ULL;

    auto load_tile = [&](int k0, int buf) {
        float* As = smem + buf * 6144;
        float* Bs = As + 2048;
        #pragma unroll
        for (int u = 0; u < 2; u++) {
            int i = tid + u*256;
            int r = i >> 5, c = (i & 31) * 4;
            unsigned d = (unsigned)__cvta_generic_to_shared(As + r*128 + c);
            CP16Z(d, AT + (size_t)(k0 + r)*Mtot + bm + c, 16);
        }
        #pragma unroll
        for (int u = 0; u < 4; u++) {
            int i = tid + u*256;
            int r = i >> 6, c = (i & 63) * 4;
            int col = bn + c;
            int p = 16;
            if (col >= N) { col = 0; p = 0; }
            unsigned d = (unsigned)__cvta_generic_to_shared(Bs + r*256 + c);
            CP16Z(d, Bm + (size_t)(k0 + r)*N + col, p);
        }
        CP_COMMIT();
    };

    int ntiles = Kd >> 4;
    load_tile(0, 0);
    for (int ti = 0; ti < ntiles; ti++) {
        if (ti > 0) __syncthreads();
        if (ti + 1 < ntiles) { load_tile((ti+1) << 4, (ti+1)&1); CP_WAIT1(); }
        else CP_WAIT0();
        __syncthreads();
        const float* As = smem + (ti&1) * 6144;
        const float* Bs = As + 2048;
        #pragma unroll
        for (int kk = 0; kk < 16; kk++) {
            float af[8], bf[16];
            *(float4*)&af[0] = *(const float4*)&As[kk*128 + ty*8];
            *(float4*)&af[4] = *(const float4*)&As[kk*128 + ty*8 + 4];
            #pragma unroll
            for (int c = 0; c < 4; c++)
                *(float4*)&bf[c*4] = *(const float4*)&Bs[kk*256 + c*64 + tx*4];
            unsigned long long bb[8];
            #pragma unroll
            for (int j = 0; j < 8; j++) PACK2(bb[j], bf[2*j], bf[2*j+1]);
            #pragma unroll
            for (int i = 0; i < 8; i++) {
                unsigned long long aa;
                PACK2(aa, af[i], af[i]);
                #pragma unroll
                for (int j = 0; j < 8; j++) FMA2(acc2[i][j], aa, bb[j]);
            }
        }
    }
    #pragma unroll
    for (int i = 0; i < 8; i++) {
        int row = bm + ty*8 + i;
        float bv = bias[row];
        #pragma unroll
        for (int c = 0; c < 4; c++) {
            int col = bn + c*64 + tx*4;
            if (col < N) {
                unsigned l0, h0, l1, h1;
                UNPACK2(l0, h0, acc2[i][2*c]);
                UNPACK2(l1, h1, acc2[i][2*c+1]);
                float4 o;
                o.x = __uint_as_float(l0) + bv;
                o.y = __uint_as_float(h0) + bv;
                o.z = __uint_as_float(l1) + bv;
                o.w = __uint_as_float(h1) + bv;
                *(float4*)&Cm[(size_t)row * N + col] = o;
            }
        }
    }
}

// ------- bf16x2-split GEMM (3 products) + masked-block broadcast ------------
__global__ __launch_bounds__(256, 1) void gemm_bf16x2(
    const __nv_bfloat16* __restrict__ AH, const __nv_bfloat16* __restrict__ AL,
    const __nv_bfloat16* __restrict__ BH0, const __nv_bfloat16* __restrict__ BL0,
    const float* __restrict__ bias, float* __restrict__ C0,
    const int* __restrict__ lens,
    int N, int Kd, size_t sB, size_t sC)
{
    extern __shared__ __align__(16) unsigned char sb[];
    const __nv_bfloat16* BH = BH0 + (size_t)blockIdx.z * sB;
    const __nv_bfloat16* BL = BL0 + (size_t)blockIdx.z * sB;
    float* Cm = C0 + (size_t)blockIdx.z * sC;
    int bm = blockIdx.y << 7, bn = blockIdx.x << 7;
    int tid = threadIdx.x, lane = tid & 31, wid = tid >> 5;

    if (bn >= lens[blockIdx.z]) {
        const float* oS = g_outS + bm;
        #pragma unroll
        for (int u = 0; u < 16; u++) {
            int i = tid + u*256;
            int r = i >> 5, c4 = (i & 31) * 4;
            int col = bn + c4;
            float v = oS[r];
            if (col < N) *(float4*)&Cm[(size_t)(bm + r) * N + col] = make_float4(v,v,v,v);
        }
        return;
    }

    int wm = (wid & 3) << 5, wn = (wid >> 2) << 6;
    int lq = lane >> 2, lr = lane & 3;
    int ntiles = Kd >> 5;

    float acc[2][8][4];
    #pragma unroll
    for (int mi = 0; mi < 2; mi++)
        #pragma unroll
        for (int ni = 0; ni < 8; ni++)
            #pragma unroll
            for (int c = 0; c < 4; c++) acc[mi][ni][c] = 0.f;

    auto load_tile = [&](int ti, int buf) {
        unsigned char* base = sb + buf * 40960;
        int k0 = ti << 5;
        #pragma unroll
        for (int r = 0; r < 8; r++) {
            int idx = r*256 + tid;
            int region = idx >> 9, w = idx & 511;
            int row = w >> 2, ch = w & 3;
            unsigned daddr = (unsigned)__cvta_generic_to_shared(base + region*10240 + row*80 + ch*16);
            const __nv_bfloat16* src; int p = 16;
            if (region == 0)      src = AH + (size_t)(bm+row)*Kd + k0 + ch*8;
            else if (region == 1) src = AL + (size_t)(bm+row)*Kd + k0 + ch*8;
            else {
                int gr = bn + row; if (gr >= N) { gr = 0; p = 0; }
                src = (region == 2 ? BH : BL) + (size_t)gr*Kd + k0 + ch*8;
            }
            CP16Z(daddr, src, p);
        }
        CP_COMMIT();
    };

    load_tile(0, 0);
    for (int ti = 0; ti < ntiles; ti++) {
        if (ti > 0) __syncthreads();
        if (ti + 1 < ntiles) { load_tile(ti+1, (ti+1)&1); CP_WAIT1(); }
        else CP_WAIT0();
        __syncthreads();
        const unsigned char* base = sb + (ti&1) * 40960;
        const unsigned char* AsH = base;
        const unsigned char* AsL = base + 10240;
        const unsigned char* BsH = base + 20480;
        const unsigned char* BsL = base + 30720;
        #pragma unroll
        for (int ks = 0; ks < 2; ks++) {
            int kb = ks*32 + lr*4;
            unsigned aH[2][4], aL[2][4], bH[8][2], bL[8][2];
            #pragma unroll
            for (int mi = 0; mi < 2; mi++) {
                int off = (wm + (mi<<4) + lq)*80 + kb;
                aH[mi][0] = *(const unsigned*)(AsH + off);
                aH[mi][1] = *(const unsigned*)(AsH + off + 8*80);
                aH[mi][2] = *(const unsigned*)(AsH + off + 16);
                aH[mi][3] = *(const unsigned*)(AsH + off + 8*80 + 16);
                aL[mi][0] = *(const unsigned*)(AsL + off);
                aL[mi][1] = *(const unsigned*)(AsL + off + 8*80);
                aL[mi][2] = *(const unsigned*)(AsL + off + 16);
                aL[mi][3] = *(const unsigned*)(AsL + off + 8*80 + 16);
            }
            #pragma unroll
            for (int ni = 0; ni < 8; ni++) {
                int off = (wn + (ni<<3) + lq)*80 + kb;
                bH[ni][0] = *(const unsigned*)(BsH + off);
                bH[ni][1] = *(const unsigned*)(BsH + off + 16);
                bL[ni][0] = *(const unsigned*)(BsL + off);
                bL[ni][1] = *(const unsigned*)(BsL + off + 16);
            }
            #pragma unroll
            for (int mi = 0; mi < 2; mi++)
                #pragma unroll
                for (int ni = 0; ni < 8; ni++) {
                    MMA_BF16(acc[mi][ni], aH[mi][0],aH[mi][1],aH[mi][2],aH[mi][3], bH[ni][0],bH[ni][1]);
                    MMA_BF16(acc[mi][ni], aH[mi][0],aH[mi][1],aH[mi][2],aH[mi][3], bL[ni][0],bL[ni][1]);
                    MMA_BF16(acc[mi][ni], aL[mi][0],aL[mi][1],aL[mi][2],aL[mi][3], bH[ni][0],bH[ni][1]);
                }
        }
    }
    #pragma unroll
    for (int mi = 0; mi < 2; mi++) {
        int row0 = bm + wm + (mi<<4) + lq;
        float b0 = bias[row0], b1 = bias[row0 + 8];
        #pragma unroll
        for (int ni = 0; ni < 8; ni++) {
            int col = bn + wn + (ni<<3) + (lr<<1);
            if (col < N) {
                float2 v0 = make_float2(acc[mi][ni][0] + b0, acc[mi][ni][1] + b0);
                float2 v1 = make_float2(acc[mi][ni][2] + b1, acc[mi][ni][3] + b1);
                *(float2*)&Cm[(size_t)row0 * N + col] = v0;
                *(float2*)&Cm[(size_t)(row0+8) * N + col] = v1;
            }
        }
    }
}

// ---------- fused RVQ scan: 1 CTA = 32 columns, 16 warps (bit-exact) --------
__global__ __launch_bounds__(512, 1) void rvq_scan(
    const int*   __restrict__ lens,
    const float* __restrict__ cbg,
    const float* __restrict__ qinb,
    const float* __restrict__ qoutb,
    float*       __restrict__ dout)
{
    extern __shared__ float sm[];
    float* s_res = sm;                 // 33792
    float* s_w   = s_res + 33792;      // 8192
    float* s_cb  = s_w + 8192;         // 8192
    float* s_cbn = s_cb + 8192;        // 1024
    float* s_red = s_cbn + 1024;       // 2048
    float* s_ze  = s_red + 2048;       // 256
    float* s_ob  = s_ze + 256;         // 1024
    float* s_mk  = s_ob + 1024;        // 32
    int*   s_sel = (int*)(s_mk + 32);
    int*   s_bi  = s_sel + 32;
    int*   s_ti  = s_bi + 32;
    int*   s_fl  = s_ti + 32;

    const int tid = threadIdx.x;
    const int lane = tid & 31, wrp = tid >> 5;   // 16 warps
    const int c0 = blockIdx.x << 5;

    if (tid < 32) {
        int c = c0 + tid;
        int b = c / T_, t = c - b * T_;
        s_bi[tid] = b; s_ti[tid] = t;
        s_mk[tid] = (t < lens[b]) ? 1.f : 0.f;
    }
    __syncthreads();
    if (tid == 0) {
        float m = 0.f;
        #pragma unroll
        for (int n = 0; n < 32; n++) m += s_mk[n];
        s_fl[0] = (m == 0.f) ? 1 : 0;
    }
    __syncthreads();

    if (s_fl[0]) {
        unsigned* sSH = (unsigned*)s_res;
        unsigned* sSL = sSH + 512;
        for (int i = tid; i < 512; i += 512) {
            sSH[i] = ((const unsigned*)g_SH)[i];
            sSL[i] = ((const unsigned*)g_SL)[i];
        }
        for (int q = wrp; q < NQ_; q += 16) {
            dout[IDX_OFF + (size_t)q*NCOL + c0 + lane] = (float)g_selm[q];
            atomicAdd(&g_commit[(q<<4) + s_bi[lane]], g_csm[q]);
        }
        __syncthreads();
        for (int i = tid; i < 32*128; i += 512) {
            int n = i >> 7, j = i & 127;
            size_t base = ((size_t)s_bi[n]*T_ + s_ti[n])*D_;
            ((uint4*)(g_qTH + base))[j] = ((const uint4*)sSH)[j];
            ((uint4*)(g_qTL + base))[j] = ((const uint4*)sSL)[j];
        }
        return;
    }

    for (int idx = tid; idx < D_*32; idx += 512) {
        int o = idx >> 5, n = idx & 31;
        s_res[o*33+n] = g_zp[(size_t)s_bi[n]*(D_*T_) + (size_t)o*T_ + s_ti[n]];
    }

    for (int q = 0; q < NQ_; q++) {
        {
            const float4* gc = (const float4*)(cbg + (size_t)q*8192);
            const float4* gq = (const float4*)(g_qin2 + q*8192);
            #pragma unroll
            for (int u = 0; u < 4; u++) {
                ((float4*)s_w)[tid + u*512]  = gq[tid + u*512];
                ((float4*)s_cb)[tid + u*512] = gc[tid + u*512];
            }
            #pragma unroll
            for (int u = 0; u < 2; u++) s_cbn[tid + u*512] = g_cbn[q*K_ + tid + u*512];
        }
        __syncthreads();

        { // phase B: warps 0-7 -> d-pairs 0-1, warps 8-15 -> d-pairs 2-3 (same i-blocks)
            int w2 = wrp & 7, dhalf = wrp >> 3;
            unsigned long long part2[2];
            part2[0] = 0ULL; part2[1] = 0ULL;
            int ib = w2 << 7;
            for (int ii = 0; ii < 128; ii += 4) {
                float r0 = s_res[(ib+ii+0)*33+lane];
                float r1 = s_res[(ib+ii+1)*33+lane];
                float r2 = s_res[(ib+ii+2)*33+lane];
                float r3 = s_res[(ib+ii+3)*33+lane];
                unsigned long long rr0, rr1, rr2, rr3;
                PACK2(rr0, r0, r0); PACK2(rr1, r1, r1);
                PACK2(rr2, r2, r2); PACK2(rr3, r3, r3);
                #pragma unroll
                for (int jj = 0; jj < 2; jj++) {
                    int j = (dhalf<<1) + jj;
                    const ulonglong2* qp = (const ulonglong2*)&s_w[j*2048 + ((ib+ii)<<1)];
                    ulonglong2 qA = qp[0];
                    ulonglong2 qB = qp[1];
                    FMA2(part2[jj], qB.y, rr3);
                    FMA2(part2[jj], qB.x, rr2);
                    FMA2(part2[jj], qA.y, rr1);
                    FMA2(part2[jj], qA.x, rr0);
                }
            }
            #pragma unroll
            for (int jj = 0; jj < 2; jj++) {
                int j = (dhalf<<1) + jj;
                unsigned lo, hi;
                UNPACK2(lo, hi, part2[jj]);
                s_red[(w2<<8)+(lane<<3)+2*j]   = __uint_as_float(lo);
                s_red[(w2<<8)+(lane<<3)+2*j+1] = __uint_as_float(hi);
            }
        }
        __syncthreads();
        if (tid < 256) { // finalize ze (identical w2-ascending chain)
            int d = tid >> 5, n = tid & 31;
            float s = 0.f;
            #pragma unroll
            for (int w2 = 0; w2 < 8; w2++) s += s_red[(w2<<8)+(n<<3)+d];
            s_ze[(n<<3)+d] = s_mk[n]*s + qinb[(q<<3)+d];
        }
        __syncthreads();

        { // phase C: 16 warps x 64 codes (ascending), identical per-code math
            float4 za = *(float4*)&s_ze[lane<<3];
            float4 zb = *(float4*)&s_ze[(lane<<3)+4];
            float zsq = za.x*za.x+za.y*za.y+za.z*za.z+za.w*za.w
                      + zb.x*zb.x+zb.y*zb.y+zb.z*zb.z+zb.w*zb.w;
            float best = 3.402823466e38f; int bk = 0;
            int kb = wrp << 6;
            #pragma unroll 4
            for (int kk = 0; kk < 64; kk++) {
                int k = kb + kk;
                float4 ca = *(float4*)&s_cb[k<<3];
                float4 cv = *(float4*)&s_cb[(k<<3)+4];
                float dot = za.x*ca.x+za.y*ca.y+za.z*ca.z+za.w*ca.w
                          + zb.x*cv.x+zb.y*cv.y+zb.z*cv.z+zb.w*cv.w;
                float d2 = zsq - 2.f*dot + s_cbn[k];
                if (d2 < best) { best = d2; bk = k; }
            }
            s_red[(wrp<<6)+(lane<<1)]   = best;
            s_red[(wrp<<6)+(lane<<1)+1] = __int_as_float(bk);
        }
        __syncthreads();

        if (wrp == 0) { // phase D: merge 16 block-bests ascending (first-min)
            int n = lane;
            float best = s_red[n<<1]; int bk = __float_as_int(s_red[(n<<1)+1]);
            #pragma unroll
            for (int w2 = 1; w2 < 16; w2++) {
                float v = s_red[(w2<<6)+(n<<1)];
                if (v < best) { best = v; bk = __float_as_int(s_red[(w2<<6)+(n<<1)+1]); }
            }
            s_sel[n] = bk;
            dout[IDX_OFF + (size_t)q*NCOL + c0 + n] = (float)bk;
            float cs = 0.f;
            #pragma unroll
            for (int d = 0; d < 8; d++) {
                float dz = s_ze[(n<<3)+d] - s_cb[(bk<<3)+d];
                cs = fmaf(dz, dz, cs);
            }
            atomicAdd(&g_commit[(q<<4) + s_bi[n]], cs);
        } else {       // warps 1-15 stage qout2 + ob
            int t2 = tid - 32;
            const float4* gw = (const float4*)(g_qout2 + q*8192);
            for (int i = t2; i < 2048; i += 480) ((float4*)s_w)[i] = gw[i];
            for (int i = t2; i < 1024; i += 480) s_ob[i] = qoutb[(q<<10) + i];
        }
        __syncthreads();

        { // phase E: 16 warps, identical per-element FMA2 chain
            int n = lane;
            int ob = wrp & 7, mhalf = wrp >> 3;
            int sel = s_sel[n];
            float4 ca = *(float4*)&s_cb[sel<<3];
            float4 cv = *(float4*)&s_cb[(sel<<3)+4];
            unsigned long long cc[8];
            PACK2(cc[0], ca.x, ca.x); PACK2(cc[1], ca.y, ca.y);
            PACK2(cc[2], ca.z, ca.z); PACK2(cc[3], ca.w, ca.w);
            PACK2(cc[4], cv.x, cv.x); PACK2(cc[5], cv.y, cv.y);
            PACK2(cc[6], cv.z, cv.z); PACK2(cc[7], cv.w, cv.w);
            #pragma unroll 4
            for (int mm = 0; mm < 32; mm++) {
                int m = (mhalf << 5) + mm;
                const float* wp = &s_w[(m*8 + ob)*16];
                ulonglong2 w01 = *(const ulonglong2*)(wp);
                ulonglong2 w23 = *(const ulonglong2*)(wp + 4);
                ulonglong2 w45 = *(const ulonglong2*)(wp + 8);
                ulonglong2 w67 = *(const ulonglong2*)(wp + 12);
                int o = (m << 4) + ob;
                unsigned long long v2;
                PACK2(v2, s_ob[o], s_ob[o+8]);
                FMA2(v2, w01.x, cc[0]); FMA2(v2, w01.y, cc[1]);
                FMA2(v2, w23.x, cc[2]); FMA2(v2, w23.y, cc[3]);
                FMA2(v2, w45.x, cc[4]); FMA2(v2, w45.y, cc[5]);
                FMA2(v2, w67.x, cc[6]); FMA2(v2, w67.y, cc[7]);
                unsigned lo, hi;
                UNPACK2(lo, hi, v2);
                s_res[o*33+n]     -= __uint_as_float(lo);
                s_res[(o+8)*33+n] -= __uint_as_float(hi);
            }
        }
        __syncthreads();
    }

    for (int idx = tid; idx < D_*32; idx += 512) {
        int o = idx >> 5, n = idx & 31;
        size_t ga = (size_t)s_bi[n]*(D_*T_) + (size_t)o*T_ + s_ti[n];
        s_res[o*33+n] = g_zp[ga] - s_res[o*33+n];
    }
    __syncthreads();
    for (int idx = tid; idx < D_*32; idx += 512) {
        int n = idx >> 10, o = idx & 1023;
        float v = s_res[o*33+n];
        __nv_bfloat16 h = __float2bfloat16(v);
        size_t a = ((size_t)s_bi[n]*T_ + s_ti[n])*D_ + o;
        g_qTH[a] = h;
        g_qTL[a] = __float2bfloat16(v - __bfloat162float(h));
    }
}

extern "C" void kernel_launch(void* const* d_in, const int* in_sizes, int n_in,
                              void* d_out, int out_size) {
    const float* z          = (const float*)d_in[0];
    const int*   lens       = (const int*)d_in[1];
    const float* in_proj_v  = (const float*)d_in[2];
    const float* in_proj_g  = (const float*)d_in[3];
    const float* in_proj_b  = (const float*)d_in[4];
    const float* out_proj_v = (const float*)d_in[5];
    const float* out_proj_g = (const float*)d_in[6];
    const float* out_proj_b = (const float*)d_in[7];
    const float* q_in_v     = (const float*)d_in[8];
    const float* q_in_g     = (const float*)d_in[9];
    const float* q_in_b     = (const float*)d_in[10];
    const float* q_out_v    = (const float*)d_in[11];
    const float* q_out_g    = (const float*)d_in[12];
    const float* q_out_b    = (const float*)d_in[13];
    const float* codebooks  = (const float*)d_in[14];
    float* dout = (float*)d_out;

    void *pWinT, *pWoutH, *pWoutL, *pzp, *pqTH, *pqTL;
    cudaGetSymbolAddress(&pWinT,  g_WinT);
    cudaGetSymbolAddress(&pWoutH, g_WoutH);
    cudaGetSymbolAddress(&pWoutL, g_WoutL);
    cudaGetSymbolAddress(&pzp,    g_zp);
    cudaGetSymbolAddress(&pqTH,   g_qTH);
    cudaGetSymbolAddress(&pqTL,   g_qTL);

    cudaFuncSetAttribute(rvq_scan,   cudaFuncAttributeMaxDynamicSharedMemorySize, 218656);
    cudaFuncSetAttribute(gemm_bf16x2, cudaFuncAttributeMaxDynamicSharedMemorySize, 81920);
    cudaFuncSetAttribute(sgemm256,   cudaFuncAttributeMaxDynamicSharedMemorySize, 49152);

    prep_all<<<4368, 32>>>(in_proj_v, in_proj_g, out_proj_v, out_proj_g,
                           q_in_v, q_in_g, q_out_v, q_out_g, codebooks);
    masked_sel<<<NQ_, 256>>>(q_in_b, codebooks);
    masked_S<<<D_/256, 256>>>(q_out_b, codebooks);

    sgemm256<<<dim3((T_+255)/256, D_/128, B_), 256, 49152>>>(
        (const float*)pWinT, z, in_proj_b, (float*)pzp, lens,
        T_, DIN, D_, (size_t)DIN*T_, (size_t)D_*T_);

    rvq_scan<<<NCOL/32, 512, 218656>>>(lens, codebooks, q_in_b, q_out_b, dout);

    gemv_S<<<D_, 32>>>(out_proj_b);
    commit_fin<<<1, 512>>>(dout);

    gemm_bf16x2<<<dim3((T_+127)/128, D_/128, B_), 256, 81920>>>(
        (const __nv_bfloat16*)pWoutH, (const __nv_bfloat16*)pWoutL,
        (const __nv_bfloat16*)pqTH, (const __nv_bfloat16*)pqTL,
        out_proj_b, dout, lens, T_, D_, (size_t)T_*D_, (size_t)D_*T_);
}

// round 14
// speedup vs baseline: 1.1381x; 1.0127x over previous
#include <cuda_runtime.h>
#include <cuda_bf16.h>
#include <math.h>

#define B_   16
#define T_   2000
#define DIN  1280
#define D_   1024
#define NQ_  32
#define K_   1024
#define NCOL (B_*T_)
#define OUT_ELEMS ((size_t)B_*D_*T_)
#define IDX_OFF   OUT_ELEMS
#define COMMIT_OFF (OUT_ELEMS + (size_t)NQ_*NCOL)

__device__ float g_WinT[DIN*D_];
__device__ __nv_bfloat16 g_WoutH[D_*D_];
__device__ __nv_bfloat16 g_WoutL[D_*D_];
__device__ float g_WoutF[D_*D_];
__device__ float g_qin2 [NQ_*8*D_];
__device__ float g_qout2[NQ_*D_*8];
__device__ float g_qoutF[NQ_*D_*8];
__device__ float g_cbn [NQ_*K_];
__device__ float g_zp  [(size_t)B_*D_*T_];
__device__ __align__(16) __nv_bfloat16 g_qTH[(size_t)B_*T_*D_];
__device__ __align__(16) __nv_bfloat16 g_qTL[(size_t)B_*T_*D_];
__device__ int   g_selm[NQ_];
__device__ float g_csm [NQ_];
__device__ float g_S   [D_];
__device__ float g_outS[D_];
__device__ __align__(16) __nv_bfloat16 g_SH[D_];
__device__ __align__(16) __nv_bfloat16 g_SL[D_];
__device__ float g_commit[NQ_*B_];

#define CP16Z(dst, src, p) asm volatile("cp.async.cg.shared.global [%0], [%1], 16, %2;\n" :: "r"(dst), "l"(src), "r"(p))
#define CP_COMMIT() asm volatile("cp.async.commit_group;\n")
#define CP_WAIT1() asm volatile("cp.async.wait_group 1;\n")
#define CP_WAIT0() asm volatile("cp.async.wait_group 0;\n")

#define MMA_BF16(d, a0,a1,a2,a3, b0,b1) \
    asm volatile("mma.sync.aligned.m16n8k16.row.col.f32.bf16.bf16.f32 " \
        "{%0,%1,%2,%3},{%4,%5,%6,%7},{%8,%9},{%0,%1,%2,%3};\n" \
        : "+f"(d[0]),"+f"(d[1]),"+f"(d[2]),"+f"(d[3]) \
        : "r"(a0),"r"(a1),"r"(a2),"r"(a3),"r"(b0),"r"(b1))

#define PACK2(o, lo, hi) \
    asm("mov.b64 %0, {%1, %2};" : "=l"(o) : "r"(__float_as_uint(lo)), "r"(__float_as_uint(hi)))
#define FMA2(acc, a, b) \
    asm("fma.rn.f32x2 %0, %1, %2, %0;" : "+l"(acc) : "l"(a), "l"(b))
#define UNPACK2(lo, hi, in) \
    asm("mov.b64 {%0, %1}, %2;" : "=r"(lo), "=r"(hi) : "l"(in))

// ---------------- fused prep ------------------------------------------------
__global__ void prep_all(const float* __restrict__ in_v,  const float* __restrict__ in_g,
                         const float* __restrict__ out_v, const float* __restrict__ out_g,
                         const float* __restrict__ qi_v,  const float* __restrict__ qi_g,
                         const float* __restrict__ qo_v,  const float* __restrict__ qo_g,
                         const float* __restrict__ cb) {
    int blk = blockIdx.x, t = threadIdx.x;
    if (blk < 1024) {
        int row = blk;
        const float* vr = in_v + (size_t)row * DIN;
        float s = 0.f;
        for (int i = t; i < DIN; i += 32) { float x = vr[i]; s = fmaf(x,x,s); }
        #pragma unroll
        for (int o = 16; o; o >>= 1) s += __shfl_xor_sync(0xffffffffu, s, o);
        float sc = in_g[row] / sqrtf(s);
        for (int i = t; i < DIN; i += 32) g_WinT[(size_t)i*D_ + row] = vr[i] * sc;
    } else if (blk < 2048) {
        int row = blk - 1024;
        const float* vr = out_v + (size_t)row * D_;
        float s = 0.f;
        for (int i = t; i < D_; i += 32) { float x = vr[i]; s = fmaf(x,x,s); }
        #pragma unroll
        for (int o = 16; o; o >>= 1) s += __shfl_xor_sync(0xffffffffu, s, o);
        float sc = out_g[row] / sqrtf(s);
        for (int i = t; i < D_; i += 32) {
            float w = vr[i] * sc;
            g_WoutF[(size_t)row*D_ + i] = w;
            __nv_bfloat16 h = __float2bfloat16(w);
            g_WoutH[(size_t)row*D_ + i] = h;
            g_WoutL[(size_t)row*D_ + i] = __float2bfloat16(w - __bfloat162float(h));
        }
    } else if (blk < 2304) {
        int row = blk - 2048; int q = row >> 3, d = row & 7;
        const float* vr = qi_v + (size_t)row * D_;
        float s = 0.f;
        for (int i = t; i < D_; i += 32) { float x = vr[i]; s = fmaf(x,x,s); }
        #pragma unroll
        for (int o = 16; o; o >>= 1) s += __shfl_xor_sync(0xffffffffu, s, o);
        float sc = qi_g[row] / sqrtf(s);
        float* ob = g_qin2 + q*8192 + (d>>1)*2048 + (d&1);
        for (int i = t; i < D_; i += 32) ob[i*2] = vr[i] * sc;
    } else if (blk < 3328) {
        int row = (blk - 2304)*32 + t;
        int q = row >> 10, o = row & 1023;
        const float* vr = qo_v + (size_t)row * 8;
        float x0=vr[0]*vr[0], x1=vr[1]*vr[1], x2=vr[2]*vr[2], x3=vr[3]*vr[3];
        float x4=vr[4]*vr[4], x5=vr[5]*vr[5], x6=vr[6]*vr[6], x7=vr[7]*vr[7];
        float s = ((x0+x4)+(x2+x6)) + ((x1+x5)+(x3+x7));
        float sc = qo_g[row] / sqrtf(s);
        float* pf = g_qoutF + (size_t)row * 8;
        float* pp = g_qout2 + q*8192 + ((o>>4)*8 + (o&7))*16 + ((o>>3)&1);
        #pragma unroll
        for (int d = 0; d < 8; d++) { float w = vr[d]*sc; pf[d] = w; pp[d*2] = w; }
    } else if (blk < 4352) {
        int i = (blk - 3328)*32 + t;
        const float* c = cb + (size_t)i * 8;
        float s = 0.f;
        #pragma unroll
        for (int d = 0; d < 8; d++) s = fmaf(c[d], c[d], s);
        g_cbn[i] = s;
    } else {
        int i = (blk - 4352)*32 + t;
        if (i < NQ_*B_) g_commit[i] = 0.f;
    }
}

// ---- masked constants ------------------------------------------------------
__global__ void masked_sel(const float* __restrict__ qinb,
                           const float* __restrict__ cbg) {
    __shared__ float sv[256];
    __shared__ int   si[256];
    int q = blockIdx.x, tid = threadIdx.x;
    float ze[8];
    #pragma unroll
    for (int d = 0; d < 8; d++) ze[d] = qinb[(q<<3)+d];
    float zsq = 0.f;
    #pragma unroll
    for (int d = 0; d < 8; d++) zsq += ze[d]*ze[d];
    const float* cbq = cbg + (size_t)q*8192;
    float best = 3.402823466e38f; int bk = 0;
    #pragma unroll
    for (int kk = 0; kk < 4; kk++) {
        int k = tid*4 + kk;
        const float* c = cbq + k*8;
        float dot = 0.f;
        #pragma unroll
        for (int d = 0; d < 8; d++) dot += ze[d]*c[d];
        float d2 = zsq - 2.f*dot + g_cbn[q*K_ + k];
        if (d2 < best) { best = d2; bk = k; }
    }
    sv[tid] = best; si[tid] = bk;
    __syncthreads();
    for (int s = 128; s; s >>= 1) {
        if (tid < s && sv[tid+s] < sv[tid]) { sv[tid] = sv[tid+s]; si[tid] = si[tid+s]; }
        __syncthreads();
    }
    if (tid == 0) {
        int s = si[0];
        g_selm[q] = s;
        const float* c = cbq + s*8;
        float cs = 0.f;
        #pragma unroll
        for (int d = 0; d < 8; d++) { float dz = ze[d]-c[d]; cs = fmaf(dz,dz,cs); }
        g_csm[q] = cs;
    }
}

__global__ void masked_S(const float* __restrict__ qoutb,
                         const float* __restrict__ cbg) {
    int o = blockIdx.x * 256 + threadIdx.x;
    float acc = 0.f;
    for (int q = 0; q < NQ_; q++) {
        int sel = g_selm[q];
        const float* c = cbg + (size_t)q*8192 + sel*8;
        const float* w = g_qoutF + ((size_t)q*D_ + o)*8;
        float v = qoutb[(q<<10)+o];
        v = fmaf(w[0],c[0],v); v = fmaf(w[1],c[1],v);
        v = fmaf(w[2],c[2],v); v = fmaf(w[3],c[3],v);
        v = fmaf(w[4],c[4],v); v = fmaf(w[5],c[5],v);
        v = fmaf(w[6],c[6],v); v = fmaf(w[7],c[7],v);
        acc += v;
    }
    g_S[o] = acc;
    __nv_bfloat16 h = __float2bfloat16(acc);
    g_SH[o] = h;
    g_SL[o] = __float2bfloat16(acc - __bfloat162float(h));
}

__global__ void commit_fin(float* __restrict__ dout) {
    if (threadIdx.x < NQ_*B_)
        dout[COMMIT_OFF + threadIdx.x] = g_commit[threadIdx.x] * (1.0f / (float)(T_*8));
}

__global__ void gemv_S(const float* __restrict__ bias) {
    int o = blockIdx.x;
    const float* w = g_WoutF + (size_t)o * D_;
    float acc = 0.f;
    for (int i = threadIdx.x; i < D_; i += 32) acc = fmaf(w[i], g_S[i], acc);
    #pragma unroll
    for (int off = 16; off; off >>= 1) acc += __shfl_xor_sync(0xffffffffu, acc, off);
    if (threadIdx.x == 0) g_outS[o] = acc + bias[o];
}

// ---- fp32 SGEMM, 128x256 tile, FFMA2, cp.async double-buffer ---------------
__global__ __launch_bounds__(256, 1) void sgemm256(
    const float* __restrict__ AT, const float* __restrict__ B0,
    const float* __restrict__ bias, float* __restrict__ C0,
    const int* __restrict__ lens,
    int N, int Kd, int Mtot, size_t strideB, size_t strideC)
{
    extern __shared__ float smem[];
    const float* Bm = B0 + (size_t)blockIdx.z * strideB;
    float* Cm = C0 + (size_t)blockIdx.z * strideC;
    int bm = blockIdx.y << 7, bn = blockIdx.x << 8;
    int tid = threadIdx.x;

    if (bn >= lens[blockIdx.z]) {
        float4 zz = make_float4(0.f,0.f,0.f,0.f);
        #pragma unroll
        for (int u = 0; u < 32; u++) {
            int i = tid + u*256;
            int r = i >> 6, c4 = (i & 63) * 4;
            int col = bn + c4;
            if (col < N) *(float4*)&Cm[(size_t)(bm + r) * N + col] = zz;
        }
        return;
    }

    int tx = tid & 15, ty = tid >> 4;
    unsigned long long acc2[8][8];
    #pragma unroll
    for (int i = 0; i < 8; i++)
        #pragma unroll
        for (int j = 0; j < 8; j++) acc2[i][j] = 0ULL;

    auto load_tile = [&](int k0, int buf) {
        float* As = smem + buf * 6144;
        float* Bs = As + 2048;
        #pragma unroll
        for (int u = 0; u < 2; u++) {
            int i = tid + u*256;
            int r = i >> 5, c = (i & 31) * 4;
            unsigned d = (unsigned)__cvta_generic_to_shared(As + r*128 + c);
            CP16Z(d, AT + (size_t)(k0 + r)*Mtot + bm + c, 16);
        }
        #pragma unroll
        for (int u = 0; u < 4; u++) {
            int i = tid + u*256;
            int r = i >> 6, c = (i & 63) * 4;
            int col = bn + c;
            int p = 16;
            if (col >= N) { col = 0; p = 0; }
            unsigned d = (unsigned)__cvta_generic_to_shared(Bs + r*256 + c);
            CP16Z(d, Bm + (size_t)(k0 + r)*N + col, p);
        }
        CP_COMMIT();
    };

    int ntiles = Kd >> 4;
    load_tile(0, 0);
    for (int ti = 0; ti < ntiles; ti++) {
        if (ti > 0) __syncthreads();
        if (ti + 1 < ntiles) { load_tile((ti+1) << 4, (ti+1)&1); CP_WAIT1(); }
        else CP_WAIT0();
        __syncthreads();
        const float* As = smem + (ti&1) * 6144;
        const float* Bs = As + 2048;
        #pragma unroll
        for (int kk = 0; kk < 16; kk++) {
            float af[8], bf[16];
            *(float4*)&af[0] = *(const float4*)&As[kk*128 + ty*8];
            *(float4*)&af[4] = *(const float4*)&As[kk*128 + ty*8 + 4];
            #pragma unroll
            for (int c = 0; c < 4; c++)
                *(float4*)&bf[c*4] = *(const float4*)&Bs[kk*256 + c*64 + tx*4];
            unsigned long long bb[8];
            #pragma unroll
            for (int j = 0; j < 8; j++) PACK2(bb[j], bf[2*j], bf[2*j+1]);
            #pragma unroll
            for (int i = 0; i < 8; i++) {
                unsigned long long aa;
                PACK2(aa, af[i], af[i]);
                #pragma unroll
                for (int j = 0; j < 8; j++) FMA2(acc2[i][j], aa, bb[j]);
            }
        }
    }
    #pragma unroll
    for (int i = 0; i < 8; i++) {
        int row = bm + ty*8 + i;
        float bv = bias[row];
        #pragma unroll
        for (int c = 0; c < 4; c++) {
            int col = bn + c*64 + tx*4;
            if (col < N) {
                unsigned l0, h0, l1, h1;
                UNPACK2(l0, h0, acc2[i][2*c]);
                UNPACK2(l1, h1, acc2[i][2*c+1]);
                float4 o;
                o.x = __uint_as_float(l0) + bv;
                o.y = __uint_as_float(h0) + bv;
                o.z = __uint_as_float(l1) + bv;
                o.w = __uint_as_float(h1) + bv;
                *(float4*)&Cm[(size_t)row * N + col] = o;
            }
        }
    }
}

// ------- bf16x2-split GEMM (3 products) + masked-block broadcast ------------
__global__ __launch_bounds__(256, 1) void gemm_bf16x2(
    const __nv_bfloat16* __restrict__ AH, const __nv_bfloat16* __restrict__ AL,
    const __nv_bfloat16* __restrict__ BH0, const __nv_bfloat16* __restrict__ BL0,
    const float* __restrict__ bias, float* __restrict__ C0,
    const int* __restrict__ lens,
    int N, int Kd, size_t sB, size_t sC)
{
    extern __shared__ __align__(16) unsigned char sb[];
    const __nv_bfloat16* BH = BH0 + (size_t)blockIdx.z * sB;
    const __nv_bfloat16* BL = BL0 + (size_t)blockIdx.z * sB;
    float* Cm = C0 + (size_t)blockIdx.z * sC;
    int bm = blockIdx.y << 7, bn = blockIdx.x << 7;
    int tid = threadIdx.x, lane = tid & 31, wid = tid >> 5;

    if (bn >= lens[blockIdx.z]) {
        const float* oS = g_outS + bm;
        #pragma unroll
        for (int u = 0; u < 16; u++) {
            int i = tid + u*256;
            int r = i >> 5, c4 = (i & 31) * 4;
            int col = bn + c4;
            float v = oS[r];
            if (col < N) *(float4*)&Cm[(size_t)(bm + r) * N + col] = make_float4(v,v,v,v);
        }
        return;
    }

    int wm = (wid & 3) << 5, wn = (wid >> 2) << 6;
    int lq = lane >> 2, lr = lane & 3;
    int ntiles = Kd >> 5;

    float acc[2][8][4];
    #pragma unroll
    for (int mi = 0; mi < 2; mi++)
        #pragma unroll
        for (int ni = 0; ni < 8; ni++)
            #pragma unroll
            for (int c = 0; c < 4; c++) acc[mi][ni][c] = 0.f;

    auto load_tile = [&](int ti, int buf) {
        unsigned char* base = sb + buf * 40960;
        int k0 = ti << 5;
        #pragma unroll
        for (int r = 0; r < 8; r++) {
            int idx = r*256 + tid;
            int region = idx >> 9, w = idx & 511;
            int row = w >> 2, ch = w & 3;
            unsigned daddr = (unsigned)__cvta_generic_to_shared(base + region*10240 + row*80 + ch*16);
            const __nv_bfloat16* src; int p = 16;
            if (region == 0)      src = AH + (size_t)(bm+row)*Kd + k0 + ch*8;
            else if (region == 1) src = AL + (size_t)(bm+row)*Kd + k0 + ch*8;
            else {
                int gr = bn + row; if (gr >= N) { gr = 0; p = 0; }
                src = (region == 2 ? BH : BL) + (size_t)gr*Kd + k0 + ch*8;
            }
            CP16Z(daddr, src, p);
        }
        CP_COMMIT();
    };

    load_tile(0, 0);
    for (int ti = 0; ti < ntiles; ti++) {
        if (ti > 0) __syncthreads();
        if (ti + 1 < ntiles) { load_tile(ti+1, (ti+1)&1); CP_WAIT1(); }
        else CP_WAIT0();
        __syncthreads();
        const unsigned char* base = sb + (ti&1) * 40960;
        const unsigned char* AsH = base;
        const unsigned char* AsL = base + 10240;
        const unsigned char* BsH = base + 20480;
        const unsigned char* BsL = base + 30720;
        #pragma unroll
        for (int ks = 0; ks < 2; ks++) {
            int kb = ks*32 + lr*4;
            unsigned aH[2][4], aL[2][4], bH[8][2], bL[8][2];
            #pragma unroll
            for (int mi = 0; mi < 2; mi++) {
                int off = (wm + (mi<<4) + lq)*80 + kb;
                aH[mi][0] = *(const unsigned*)(AsH + off);
                aH[mi][1] = *(const unsigned*)(AsH + off + 8*80);
                aH[mi][2] = *(const unsigned*)(AsH + off + 16);
                aH[mi][3] = *(const unsigned*)(AsH + off + 8*80 + 16);
                aL[mi][0] = *(const unsigned*)(AsL + off);
                aL[mi][1] = *(const unsigned*)(AsL + off + 8*80);
                aL[mi][2] = *(const unsigned*)(AsL + off + 16);
                aL[mi][3] = *(const unsigned*)(AsL + off + 8*80 + 16);
            }
            #pragma unroll
            for (int ni = 0; ni < 8; ni++) {
                int off = (wn + (ni<<3) + lq)*80 + kb;
                bH[ni][0] = *(const unsigned*)(BsH + off);
                bH[ni][1] = *(const unsigned*)(BsH + off + 16);
                bL[ni][0] = *(const unsigned*)(BsL + off);
                bL[ni][1] = *(const unsigned*)(BsL + off + 16);
            }
            #pragma unroll
            for (int mi = 0; mi < 2; mi++)
                #pragma unroll
                for (int ni = 0; ni < 8; ni++) {
                    MMA_BF16(acc[mi][ni], aH[mi][0],aH[mi][1],aH[mi][2],aH[mi][3], bH[ni][0],bH[ni][1]);
                    MMA_BF16(acc[mi][ni], aH[mi][0],aH[mi][1],aH[mi][2],aH[mi][3], bL[ni][0],bL[ni][1]);
                    MMA_BF16(acc[mi][ni], aL[mi][0],aL[mi][1],aL[mi][2],aL[mi][3], bH[ni][0],bH[ni][1]);
                }
        }
    }
    #pragma unroll
    for (int mi = 0; mi < 2; mi++) {
        int row0 = bm + wm + (mi<<4) + lq;
        float b0 = bias[row0], b1 = bias[row0 + 8];
        #pragma unroll
        for (int ni = 0; ni < 8; ni++) {
            int col = bn + wn + (ni<<3) + (lr<<1);
            if (col < N) {
                float2 v0 = make_float2(acc[mi][ni][0] + b0, acc[mi][ni][1] + b0);
                float2 v1 = make_float2(acc[mi][ni][2] + b1, acc[mi][ni][3] + b1);
                *(float2*)&Cm[(size_t)row0 * N + col] = v0;
                *(float2*)&Cm[(size_t)(row0+8) * N + col] = v1;
            }
        }
    }
}

// ---------- fused RVQ scan: 16 warps, cp.async-pipelined staging ------------
__global__ __launch_bounds__(512, 1) void rvq_scan(
    const int*   __restrict__ lens,
    const float* __restrict__ cbg,
    const float* __restrict__ qinb,
    const float* __restrict__ qoutb,
    float*       __restrict__ dout)
{
    extern __shared__ float sm[];
    float* s_res = sm;                 // 33792
    float* s_w   = s_res + 33792;      // 8192  (qout2 only)
    float* s_cb  = s_w + 8192;         // 8192
    float* s_cbn = s_cb + 8192;        // 1024
    float* s_red = s_cbn + 1024;       // 2048
    float* s_ze  = s_red + 2048;       // 256
    float* s_ob  = s_ze + 256;         // 1024
    float* s_mk  = s_ob + 1024;        // 32
    int*   s_sel = (int*)(s_mk + 32);
    int*   s_bi  = s_sel + 32;
    int*   s_ti  = s_bi + 32;
    int*   s_fl  = s_ti + 32;

    const int tid = threadIdx.x;
    const int lane = tid & 31, wrp = tid >> 5;
    const int c0 = blockIdx.x << 5;

    if (tid < 32) {
        int c = c0 + tid;
        int b = c / T_, t = c - b * T_;
        s_bi[tid] = b; s_ti[tid] = t;
        s_mk[tid] = (t < lens[b]) ? 1.f : 0.f;
    }
    __syncthreads();
    if (tid == 0) {
        float m = 0.f;
        #pragma unroll
        for (int n = 0; n < 32; n++) m += s_mk[n];
        s_fl[0] = (m == 0.f) ? 1 : 0;
    }
    __syncthreads();

    if (s_fl[0]) {
        unsigned* sSH = (unsigned*)s_res;
        unsigned* sSL = sSH + 512;
        for (int i = tid; i < 512; i += 512) {
            sSH[i] = ((const unsigned*)g_SH)[i];
            sSL[i] = ((const unsigned*)g_SL)[i];
        }
        for (int q = wrp; q < NQ_; q += 16) {
            dout[IDX_OFF + (size_t)q*NCOL + c0 + lane] = (float)g_selm[q];
            atomicAdd(&g_commit[(q<<4) + s_bi[lane]], g_csm[q]);
        }
        __syncthreads();
        for (int i = tid; i < 32*128; i += 512) {
            int n = i >> 7, j = i & 127;
            size_t base = ((size_t)s_bi[n]*T_ + s_ti[n])*D_;
            ((uint4*)(g_qTH + base))[j] = ((const uint4*)sSH)[j];
            ((uint4*)(g_qTL + base))[j] = ((const uint4*)sSL)[j];
        }
        return;
    }

    // staging via cp.async: cb + cbn + qout2 + ob for quantizer q
    auto stage = [&](int q) {
        const float4* gc = (const float4*)(cbg + (size_t)q*8192);
        const float4* gw = (const float4*)(g_qout2 + q*8192);
        #pragma unroll
        for (int u = 0; u < 4; u++) {
            unsigned dcb = (unsigned)__cvta_generic_to_shared(&((float4*)s_cb)[tid + u*512]);
            CP16Z(dcb, gc + tid + u*512, 16);
            unsigned dw = (unsigned)__cvta_generic_to_shared(&((float4*)s_w)[tid + u*512]);
            CP16Z(dw, gw + tid + u*512, 16);
        }
        if (tid < 256) {
            unsigned dn = (unsigned)__cvta_generic_to_shared(&((float4*)s_cbn)[tid]);
            CP16Z(dn, ((const float4*)(g_cbn + q*K_)) + tid, 16);
        } else {
            int t2 = tid - 256;
            unsigned dob = (unsigned)__cvta_generic_to_shared(&((float4*)s_ob)[t2]);
            CP16Z(dob, ((const float4*)(qoutb + (q<<10))) + t2, 16);
        }
        CP_COMMIT();
    };

    stage(0);   // overlap q0 staging with residual gmem load

    for (int idx = tid; idx < D_*32; idx += 512) {
        int o = idx >> 5, n = idx & 31;
        s_res[o*33+n] = g_zp[(size_t)s_bi[n]*(D_*T_) + (size_t)o*T_ + s_ti[n]];
    }
    __syncthreads();

    for (int q = 0; q < NQ_; q++) {
        { // phase B: qin2 read straight from L2 (broadcast), bit-identical chain
            int w2 = wrp & 7, dhalf = wrp >> 3;
            const ulonglong2* qg = (const ulonglong2*)(g_qin2 + q*8192);
            unsigned long long part2[2];
            part2[0] = 0ULL; part2[1] = 0ULL;
            int ib = w2 << 7;
            for (int ii = 0; ii < 128; ii += 4) {
                float r0 = s_res[(ib+ii+0)*33+lane];
                float r1 = s_res[(ib+ii+1)*33+lane];
                float r2 = s_res[(ib+ii+2)*33+lane];
                float r3 = s_res[(ib+ii+3)*33+lane];
                unsigned long long rr0, rr1, rr2, rr3;
                PACK2(rr0, r0, r0); PACK2(rr1, r1, r1);
                PACK2(rr2, r2, r2); PACK2(rr3, r3, r3);
                #pragma unroll
                for (int jj = 0; jj < 2; jj++) {
                    int j = (dhalf<<1) + jj;
                    const ulonglong2* qp = qg + j*512 + ((ib+ii)>>1);
                    ulonglong2 qA = __ldg(qp);
                    ulonglong2 qB = __ldg(qp + 1);
                    FMA2(part2[jj], qB.y, rr3);
                    FMA2(part2[jj], qB.x, rr2);
                    FMA2(part2[jj], qA.y, rr1);
                    FMA2(part2[jj], qA.x, rr0);
                }
            }
            #pragma unroll
            for (int jj = 0; jj < 2; jj++) {
                int j = (dhalf<<1) + jj;
                unsigned lo, hi;
                UNPACK2(lo, hi, part2[jj]);
                s_red[(w2<<8)+(lane<<3)+2*j]   = __uint_as_float(lo);
                s_red[(w2<<8)+(lane<<3)+2*j+1] = __uint_as_float(hi);
            }
        }
        __syncthreads();
        if (tid < 256) { // finalize ze
            int d = tid >> 5, n = tid & 31;
            float s = 0.f;
            #pragma unroll
            for (int w2 = 0; w2 < 8; w2++) s += s_red[(w2<<8)+(n<<3)+d];
            s_ze[(n<<3)+d] = s_mk[n]*s + qinb[(q<<3)+d];
        }
        CP_WAIT0();         // staged cb/cbn/qout2/ob have landed
        __syncthreads();

        { // phase C: per-warp argmin over 64 codes (unchanged math)
            float4 za = *(float4*)&s_ze[lane<<3];
            float4 zb = *(float4*)&s_ze[(lane<<3)+4];
            float zsq = za.x*za.x+za.y*za.y+za.z*za.z+za.w*za.w
                      + zb.x*zb.x+zb.y*zb.y+zb.z*zb.z+zb.w*zb.w;
            float best = 3.402823466e38f; int bk = 0;
            int kb = wrp << 6;
            #pragma unroll 4
            for (int kk = 0; kk < 64; kk++) {
                int k = kb + kk;
                float4 ca = *(float4*)&s_cb[k<<3];
                float4 cv = *(float4*)&s_cb[(k<<3)+4];
                float dot = za.x*ca.x+za.y*ca.y+za.z*ca.z+za.w*ca.w
                          + zb.x*cv.x+zb.y*cv.y+zb.z*cv.z+zb.w*cv.w;
                float d2 = zsq - 2.f*dot + s_cbn[k];
                if (d2 < best) { best = d2; bk = k; }
            }
            s_red[(wrp<<6)+(lane<<1)]   = best;
            s_red[(wrp<<6)+(lane<<1)+1] = __int_as_float(bk);
        }
        __syncthreads();

        if (wrp == 0) { // phase D: 16-way ascending merge (first-min exact)
            int n = lane;
            float best = s_red[n<<1]; int bk = __float_as_int(s_red[(n<<1)+1]);
            #pragma unroll
            for (int w2 = 1; w2 < 16; w2++) {
                float v = s_red[(w2<<6)+(n<<1)];
                if (v < best) { best = v; bk = __float_as_int(s_red[(w2<<6)+(n<<1)+1]); }
            }
            s_sel[n] = bk;
            dout[IDX_OFF + (size_t)q*NCOL + c0 + n] = (float)bk;
            float cs = 0.f;
            #pragma unroll
            for (int d = 0; d < 8; d++) {
                float dz = s_ze[(n<<3)+d] - s_cb[(bk<<3)+d];
                cs = fmaf(dz, dz, cs);
            }
            atomicAdd(&g_commit[(q<<4) + s_bi[n]], cs);
        }
        __syncthreads();

        { // phase E: FFMA2 over (o,o+8) pairs (unchanged chain)
            int n = lane;
            int ob = wrp & 7, mhalf = wrp >> 3;
            int sel = s_sel[n];
            float4 ca = *(float4*)&s_cb[sel<<3];
            float4 cv = *(float4*)&s_cb[(sel<<3)+4];
            unsigned long long cc[8];
            PACK2(cc[0], ca.x, ca.x); PACK2(cc[1], ca.y, ca.y);
            PACK2(cc[2], ca.z, ca.z); PACK2(cc[3], ca.w, ca.w);
            PACK2(cc[4], cv.x, cv.x); PACK2(cc[5], cv.y, cv.y);
            PACK2(cc[6], cv.z, cv.z); PACK2(cc[7], cv.w, cv.w);
            #pragma unroll 4
            for (int mm = 0; mm < 32; mm++) {
                int m = (mhalf << 5) + mm;
                const float* wp = &s_w[(m*8 + ob)*16];
                ulonglong2 w01 = *(const ulonglong2*)(wp);
                ulonglong2 w23 = *(const ulonglong2*)(wp + 4);
                ulonglong2 w45 = *(const ulonglong2*)(wp + 8);
                ulonglong2 w67 = *(const ulonglong2*)(wp + 12);
                int o = (m << 4) + ob;
                unsigned long long v2;
                PACK2(v2, s_ob[o], s_ob[o+8]);
                FMA2(v2, w01.x, cc[0]); FMA2(v2, w01.y, cc[1]);
                FMA2(v2, w23.x, cc[2]); FMA2(v2, w23.y, cc[3]);
                FMA2(v2, w45.x, cc[4]); FMA2(v2, w45.y, cc[5]);
                FMA2(v2, w67.x, cc[6]); FMA2(v2, w67.y, cc[7]);
                unsigned lo, hi;
                UNPACK2(lo, hi, v2);
                s_res[o*33+n]     -= __uint_as_float(lo);
                s_res[(o+8)*33+n] -= __uint_as_float(hi);
            }
        }
        __syncthreads();
        if (q + 1 < NQ_) stage(q + 1);   // lands during next phase B
    }

    for (int idx = tid; idx < D_*32; idx += 512) {
        int o = idx >> 5, n = idx & 31;
        size_t ga = (size_t)s_bi[n]*(D_*T_) + (size_t)o*T_ + s_ti[n];
        s_res[o*33+n] = g_zp[ga] - s_res[o*33+n];
    }
    __syncthreads();
    for (int idx = tid; idx < D_*32; idx += 512) {
        int n = idx >> 10, o = idx & 1023;
        float v = s_res[o*33+n];
        __nv_bfloat16 h = __float2bfloat16(v);
        size_t a = ((size_t)s_bi[n]*T_ + s_ti[n])*D_ + o;
        g_qTH[a] = h;
        g_qTL[a] = __float2bfloat16(v - __bfloat162float(h));
    }
}

extern "C" void kernel_launch(void* const* d_in, const int* in_sizes, int n_in,
                              void* d_out, int out_size) {
    const float* z          = (const float*)d_in[0];
    const int*   lens       = (const int*)d_in[1];
    const float* in_proj_v  = (const float*)d_in[2];
    const float* in_proj_g  = (const float*)d_in[3];
    const float* in_proj_b  = (const float*)d_in[4];
    const float* out_proj_v = (const float*)d_in[5];
    const float* out_proj_g = (const float*)d_in[6];
    const float* out_proj_b = (const float*)d_in[7];
    const float* q_in_v     = (const float*)d_in[8];
    const float* q_in_g     = (const float*)d_in[9];
    const float* q_in_b     = (const float*)d_in[10];
    const float* q_out_v    = (const float*)d_in[11];
    const float* q_out_g    = (const float*)d_in[12];
    const float* q_out_b    = (const float*)d_in[13];
    const float* codebooks  = (const float*)d_in[14];
    float* dout = (float*)d_out;

    void *pWinT, *pWoutH, *pWoutL, *pzp, *pqTH, *pqTL;
    cudaGetSymbolAddress(&pWinT,  g_WinT);
    cudaGetSymbolAddress(&pWoutH, g_WoutH);
    cudaGetSymbolAddress(&pWoutL, g_WoutL);
    cudaGetSymbolAddress(&pzp,    g_zp);
    cudaGetSymbolAddress(&pqTH,   g_qTH);
    cudaGetSymbolAddress(&pqTL,   g_qTL);

    cudaFuncSetAttribute(rvq_scan,   cudaFuncAttributeMaxDynamicSharedMemorySize, 218656);
    cudaFuncSetAttribute(gemm_bf16x2, cudaFuncAttributeMaxDynamicSharedMemorySize, 81920);
    cudaFuncSetAttribute(sgemm256,   cudaFuncAttributeMaxDynamicSharedMemorySize, 49152);

    prep_all<<<4368, 32>>>(in_proj_v, in_proj_g, out_proj_v, out_proj_g,
                           q_in_v, q_in_g, q_out_v, q_out_g, codebooks);
    masked_sel<<<NQ_, 256>>>(q_in_b, codebooks);
    masked_S<<<D_/256, 256>>>(q_out_b, codebooks);

    sgemm256<<<dim3((T_+255)/256, D_/128, B_), 256, 49152>>>(
        (const float*)pWinT, z, in_proj_b, (float*)pzp, lens,
        T_, DIN, D_, (size_t)DIN*T_, (size_t)D_*T_);

    rvq_scan<<<NCOL/32, 512, 218656>>>(lens, codebooks, q_in_b, q_out_b, dout);

    gemv_S<<<D_, 32>>>(out_proj_b);
    commit_fin<<<1, 512>>>(dout);

    gemm_bf16x2<<<dim3((T_+127)/128, D_/128, B_), 256, 81920>>>(
        (const __nv_bfloat16*)pWoutH, (const __nv_bfloat16*)pWoutL,
        (const __nv_bfloat16*)pqTH, (const __nv_bfloat16*)pqTL,
        out_proj_b, dout, lens, T_, D_, (size_t)T_*D_, (size_t)D_*T_);
}

// round 15
// speedup vs baseline: 1.1542x; 1.0141x over previous
#include <cuda_runtime.h>
#include <cuda_bf16.h>
#include <math.h>

#define B_   16
#define T_   2000
#define DIN  1280
#define D_   1024
#define NQ_  32
#define K_   1024
#define NCOL (B_*T_)
#define OUT_ELEMS ((size_t)B_*D_*T_)
#define IDX_OFF   OUT_ELEMS
#define COMMIT_OFF (OUT_ELEMS + (size_t)NQ_*NCOL)

__device__ float g_WinT[DIN*D_];
__device__ __nv_bfloat16 g_WoutH[D_*D_];
__device__ __nv_bfloat16 g_WoutL[D_*D_];
__device__ float g_WoutF[D_*D_];
__device__ float g_qin2 [NQ_*8*D_];
__device__ float g_qout2[NQ_*D_*8];
__device__ float g_qoutF[NQ_*D_*8];
__device__ float g_cbn [NQ_*K_];
__device__ float g_zp  [(size_t)B_*D_*T_];
__device__ __align__(16) __nv_bfloat16 g_qTH[(size_t)B_*T_*D_];
__device__ __align__(16) __nv_bfloat16 g_qTL[(size_t)B_*T_*D_];
__device__ int   g_selm[NQ_];
__device__ float g_csm [NQ_];
__device__ float g_S   [D_];
__device__ float g_outS[D_];
__device__ float g_commit[NQ_*B_];

#define CP16Z(dst, src, p) asm volatile("cp.async.cg.shared.global [%0], [%1], 16, %2;\n" :: "r"(dst), "l"(src), "r"(p))
#define CP_COMMIT() asm volatile("cp.async.commit_group;\n")
#define CP_WAIT1() asm volatile("cp.async.wait_group 1;\n")
#define CP_WAIT0() asm volatile("cp.async.wait_group 0;\n")

#define MMA_BF16(d, a0,a1,a2,a3, b0,b1) \
    asm volatile("mma.sync.aligned.m16n8k16.row.col.f32.bf16.bf16.f32 " \
        "{%0,%1,%2,%3},{%4,%5,%6,%7},{%8,%9},{%0,%1,%2,%3};\n" \
        : "+f"(d[0]),"+f"(d[1]),"+f"(d[2]),"+f"(d[3]) \
        : "r"(a0),"r"(a1),"r"(a2),"r"(a3),"r"(b0),"r"(b1))

#define PACK2(o, lo, hi) \
    asm("mov.b64 %0, {%1, %2};" : "=l"(o) : "r"(__float_as_uint(lo)), "r"(__float_as_uint(hi)))
#define FMA2(acc, a, b) \
    asm("fma.rn.f32x2 %0, %1, %2, %0;" : "+l"(acc) : "l"(a), "l"(b))
#define UNPACK2(lo, hi, in) \
    asm("mov.b64 {%0, %1}, %2;" : "=r"(lo), "=r"(hi) : "l"(in))

// ---------------- fused prep ------------------------------------------------
__global__ void prep_all(const float* __restrict__ in_v,  const float* __restrict__ in_g,
                         const float* __restrict__ out_v, const float* __restrict__ out_g,
                         const float* __restrict__ qi_v,  const float* __restrict__ qi_g,
                         const float* __restrict__ qo_v,  const float* __restrict__ qo_g,
                         const float* __restrict__ cb) {
    int blk = blockIdx.x, t = threadIdx.x;
    if (blk < 1024) {
        int row = blk;
        const float* vr = in_v + (size_t)row * DIN;
        float s = 0.f;
        for (int i = t; i < DIN; i += 32) { float x = vr[i]; s = fmaf(x,x,s); }
        #pragma unroll
        for (int o = 16; o; o >>= 1) s += __shfl_xor_sync(0xffffffffu, s, o);
        float sc = in_g[row] / sqrtf(s);
        for (int i = t; i < DIN; i += 32) g_WinT[(size_t)i*D_ + row] = vr[i] * sc;
    } else if (blk < 2048) {
        int row = blk - 1024;
        const float* vr = out_v + (size_t)row * D_;
        float s = 0.f;
        for (int i = t; i < D_; i += 32) { float x = vr[i]; s = fmaf(x,x,s); }
        #pragma unroll
        for (int o = 16; o; o >>= 1) s += __shfl_xor_sync(0xffffffffu, s, o);
        float sc = out_g[row] / sqrtf(s);
        for (int i = t; i < D_; i += 32) {
            float w = vr[i] * sc;
            g_WoutF[(size_t)row*D_ + i] = w;
            __nv_bfloat16 h = __float2bfloat16(w);
            g_WoutH[(size_t)row*D_ + i] = h;
            g_WoutL[(size_t)row*D_ + i] = __float2bfloat16(w - __bfloat162float(h));
        }
    } else if (blk < 2304) {
        int row = blk - 2048; int q = row >> 3, d = row & 7;
        const float* vr = qi_v + (size_t)row * D_;
        float s = 0.f;
        for (int i = t; i < D_; i += 32) { float x = vr[i]; s = fmaf(x,x,s); }
        #pragma unroll
        for (int o = 16; o; o >>= 1) s += __shfl_xor_sync(0xffffffffu, s, o);
        float sc = qi_g[row] / sqrtf(s);
        float* ob = g_qin2 + q*8192 + (d>>1)*2048 + (d&1);
        for (int i = t; i < D_; i += 32) ob[i*2] = vr[i] * sc;
    } else if (blk < 3328) {
        int row = (blk - 2304)*32 + t;
        int q = row >> 10, o = row & 1023;
        const float* vr = qo_v + (size_t)row * 8;
        float x0=vr[0]*vr[0], x1=vr[1]*vr[1], x2=vr[2]*vr[2], x3=vr[3]*vr[3];
        float x4=vr[4]*vr[4], x5=vr[5]*vr[5], x6=vr[6]*vr[6], x7=vr[7]*vr[7];
        float s = ((x0+x4)+(x2+x6)) + ((x1+x5)+(x3+x7));
        float sc = qo_g[row] / sqrtf(s);
        float* pf = g_qoutF + (size_t)row * 8;
        float* pp = g_qout2 + q*8192 + ((o>>4)*8 + (o&7))*16 + ((o>>3)&1);
        #pragma unroll
        for (int d = 0; d < 8; d++) { float w = vr[d]*sc; pf[d] = w; pp[d*2] = w; }
    } else if (blk < 4352) {
        int i = (blk - 3328)*32 + t;
        const float* c = cb + (size_t)i * 8;
        float s = 0.f;
        #pragma unroll
        for (int d = 0; d < 8; d++) s = fmaf(c[d], c[d], s);
        g_cbn[i] = s;
    } else {
        int i = (blk - 4352)*32 + t;
        if (i < NQ_*B_) g_commit[i] = 0.f;
    }
}

// ---- masked constants: self-contained (cbn recomputed with prep's chain) ---
__global__ void masked_sel(const float* __restrict__ qinb,
                           const float* __restrict__ cbg) {
    __shared__ float sv[256];
    __shared__ int   si[256];
    int q = blockIdx.x, tid = threadIdx.x;
    float ze[8];
    #pragma unroll
    for (int d = 0; d < 8; d++) ze[d] = qinb[(q<<3)+d];
    float zsq = 0.f;
    #pragma unroll
    for (int d = 0; d < 8; d++) zsq += ze[d]*ze[d];
    const float* cbq = cbg + (size_t)q*8192;
    float best = 3.402823466e38f; int bk = 0;
    #pragma unroll
    for (int kk = 0; kk < 4; kk++) {
        int k = tid*4 + kk;
        const float* c = cbq + k*8;
        float dot = 0.f;
        #pragma unroll
        for (int d = 0; d < 8; d++) dot += ze[d]*c[d];
        float cbn = 0.f;
        #pragma unroll
        for (int d = 0; d < 8; d++) cbn = fmaf(c[d], c[d], cbn);
        float d2 = zsq - 2.f*dot + cbn;
        if (d2 < best) { best = d2; bk = k; }
    }
    sv[tid] = best; si[tid] = bk;
    __syncthreads();
    for (int s = 128; s; s >>= 1) {
        if (tid < s && sv[tid+s] < sv[tid]) { sv[tid] = sv[tid+s]; si[tid] = si[tid+s]; }
        __syncthreads();
    }
    if (tid == 0) {
        int s = si[0];
        g_selm[q] = s;
        const float* c = cbq + s*8;
        float cs = 0.f;
        #pragma unroll
        for (int d = 0; d < 8; d++) { float dz = ze[d]-c[d]; cs = fmaf(dz,dz,cs); }
        g_csm[q] = cs;
    }
}

__global__ void commit_fin(float* __restrict__ dout) {
    if (threadIdx.x < NQ_*B_)
        dout[COMMIT_OFF + threadIdx.x] = g_commit[threadIdx.x] * (1.0f / (float)(T_*8));
}

__global__ void gemv_S(const float* __restrict__ bias) {
    int o = blockIdx.x;
    const float* w = g_WoutF + (size_t)o * D_;
    float acc = 0.f;
    for (int i = threadIdx.x; i < D_; i += 32) acc = fmaf(w[i], g_S[i], acc);
    #pragma unroll
    for (int off = 16; off; off >>= 1) acc += __shfl_xor_sync(0xffffffffu, acc, off);
    if (threadIdx.x == 0) g_outS[o] = acc + bias[o];
}

// ---- fp32 SGEMM, 128x256 tile, FFMA2, 3-stage cp.async pipeline ------------
__global__ __launch_bounds__(256, 1) void sgemm256(
    const float* __restrict__ AT, const float* __restrict__ B0,
    const float* __restrict__ bias, float* __restrict__ C0,
    const int* __restrict__ lens,
    int N, int Kd, int Mtot, size_t strideB, size_t strideC)
{
    extern __shared__ float smem[];
    const float* Bm = B0 + (size_t)blockIdx.z * strideB;
    float* Cm = C0 + (size_t)blockIdx.z * strideC;
    int bm = blockIdx.y << 7, bn = blockIdx.x << 8;
    int tid = threadIdx.x;

    if (bn >= lens[blockIdx.z]) {
        float4 zz = make_float4(0.f,0.f,0.f,0.f);
        #pragma unroll
        for (int u = 0; u < 32; u++) {
            int i = tid + u*256;
            int r = i >> 6, c4 = (i & 63) * 4;
            int col = bn + c4;
            if (col < N) *(float4*)&Cm[(size_t)(bm + r) * N + col] = zz;
        }
        return;
    }

    int tx = tid & 15, ty = tid >> 4;
    unsigned long long acc2[8][8];
    #pragma unroll
    for (int i = 0; i < 8; i++)
        #pragma unroll
        for (int j = 0; j < 8; j++) acc2[i][j] = 0ULL;

    auto load_tile = [&](int k0, int buf) {
        float* As = smem + buf * 6144;
        float* Bs = As + 2048;
        #pragma unroll
        for (int u = 0; u < 2; u++) {
            int i = tid + u*256;
            int r = i >> 5, c = (i & 31) * 4;
            unsigned d = (unsigned)__cvta_generic_to_shared(As + r*128 + c);
            CP16Z(d, AT + (size_t)(k0 + r)*Mtot + bm + c, 16);
        }
        #pragma unroll
        for (int u = 0; u < 4; u++) {
            int i = tid + u*256;
            int r = i >> 6, c = (i & 63) * 4;
            int col = bn + c;
            int p = 16;
            if (col >= N) { col = 0; p = 0; }
            unsigned d = (unsigned)__cvta_generic_to_shared(Bs + r*256 + c);
            CP16Z(d, Bm + (size_t)(k0 + r)*N + col, p);
        }
        CP_COMMIT();
    };

    int ntiles = Kd >> 4;
    load_tile(0, 0);
    load_tile(16, 1);
    int buf = 0;
    for (int ti = 0; ti < ntiles; ti++) {
        if (ti + 1 < ntiles) CP_WAIT1(); else CP_WAIT0();
        __syncthreads();
        const float* As = smem + buf * 6144;
        const float* Bs = As + 2048;
        #pragma unroll
        for (int kk = 0; kk < 16; kk++) {
            float af[8], bf[16];
            *(float4*)&af[0] = *(const float4*)&As[kk*128 + ty*8];
            *(float4*)&af[4] = *(const float4*)&As[kk*128 + ty*8 + 4];
            #pragma unroll
            for (int c = 0; c < 4; c++)
                *(float4*)&bf[c*4] = *(const float4*)&Bs[kk*256 + c*64 + tx*4];
            unsigned long long bb[8];
            #pragma unroll
            for (int j = 0; j < 8; j++) PACK2(bb[j], bf[2*j], bf[2*j+1]);
            #pragma unroll
            for (int i = 0; i < 8; i++) {
                unsigned long long aa;
                PACK2(aa, af[i], af[i]);
                #pragma unroll
                for (int j = 0; j < 8; j++) FMA2(acc2[i][j], aa, bb[j]);
            }
        }
        if (ti + 2 < ntiles) {
            int nbuf = buf + 2; if (nbuf >= 3) nbuf -= 3;
            load_tile((ti+2) << 4, nbuf);
        }
        if (++buf == 3) buf = 0;
    }
    #pragma unroll
    for (int i = 0; i < 8; i++) {
        int row = bm + ty*8 + i;
        float bv = bias[row];
        #pragma unroll
        for (int c = 0; c < 4; c++) {
            int col = bn + c*64 + tx*4;
            if (col < N) {
                unsigned l0, h0, l1, h1;
                UNPACK2(l0, h0, acc2[i][2*c]);
                UNPACK2(l1, h1, acc2[i][2*c+1]);
                float4 o;
                o.x = __uint_as_float(l0) + bv;
                o.y = __uint_as_float(h0) + bv;
                o.z = __uint_as_float(l1) + bv;
                o.w = __uint_as_float(h1) + bv;
                *(float4*)&Cm[(size_t)row * N + col] = o;
            }
        }
    }
}

// ------- bf16x2-split GEMM (3 products), 3-stage pipeline -------------------
__global__ __launch_bounds__(256, 1) void gemm_bf16x2(
    const __nv_bfloat16* __restrict__ AH, const __nv_bfloat16* __restrict__ AL,
    const __nv_bfloat16* __restrict__ BH0, const __nv_bfloat16* __restrict__ BL0,
    const float* __restrict__ bias, float* __restrict__ C0,
    const int* __restrict__ lens,
    int N, int Kd, size_t sB, size_t sC)
{
    extern __shared__ __align__(16) unsigned char sb[];
    const __nv_bfloat16* BH = BH0 + (size_t)blockIdx.z * sB;
    const __nv_bfloat16* BL = BL0 + (size_t)blockIdx.z * sB;
    float* Cm = C0 + (size_t)blockIdx.z * sC;
    int bm = blockIdx.y << 7, bn = blockIdx.x << 7;
    int tid = threadIdx.x, lane = tid & 31, wid = tid >> 5;

    if (bn >= lens[blockIdx.z]) {
        const float* oS = g_outS + bm;
        #pragma unroll
        for (int u = 0; u < 16; u++) {
            int i = tid + u*256;
            int r = i >> 5, c4 = (i & 31) * 4;
            int col = bn + c4;
            float v = oS[r];
            if (col < N) *(float4*)&Cm[(size_t)(bm + r) * N + col] = make_float4(v,v,v,v);
        }
        return;
    }

    int wm = (wid & 3) << 5, wn = (wid >> 2) << 6;
    int lq = lane >> 2, lr = lane & 3;
    int ntiles = Kd >> 5;

    float acc[2][8][4];
    #pragma unroll
    for (int mi = 0; mi < 2; mi++)
        #pragma unroll
        for (int ni = 0; ni < 8; ni++)
            #pragma unroll
            for (int c = 0; c < 4; c++) acc[mi][ni][c] = 0.f;

    auto load_tile = [&](int ti, int buf) {
        unsigned char* base = sb + buf * 40960;
        int k0 = ti << 5;
        #pragma unroll
        for (int r = 0; r < 8; r++) {
            int idx = r*256 + tid;
            int region = idx >> 9, w = idx & 511;
            int row = w >> 2, ch = w & 3;
            unsigned daddr = (unsigned)__cvta_generic_to_shared(base + region*10240 + row*80 + ch*16);
            const __nv_bfloat16* src; int p = 16;
            if (region == 0)      src = AH + (size_t)(bm+row)*Kd + k0 + ch*8;
            else if (region == 1) src = AL + (size_t)(bm+row)*Kd + k0 + ch*8;
            else {
                int gr = bn + row; if (gr >= N) { gr = 0; p = 0; }
                src = (region == 2 ? BH : BL) + (size_t)gr*Kd + k0 + ch*8;
            }
            CP16Z(daddr, src, p);
        }
        CP_COMMIT();
    };

    load_tile(0, 0);
    load_tile(1, 1);
    int buf = 0;
    for (int ti = 0; ti < ntiles; ti++) {
        if (ti + 1 < ntiles) CP_WAIT1(); else CP_WAIT0();
        __syncthreads();
        const unsigned char* base = sb + buf * 40960;
        const unsigned char* AsH = base;
        const unsigned char* AsL = base + 10240;
        const unsigned char* BsH = base + 20480;
        const unsigned char* BsL = base + 30720;
        #pragma unroll
        for (int ks = 0; ks < 2; ks++) {
            int kb = ks*32 + lr*4;
            unsigned aH[2][4], aL[2][4], bH[8][2], bL[8][2];
            #pragma unroll
            for (int mi = 0; mi < 2; mi++) {
                int off = (wm + (mi<<4) + lq)*80 + kb;
                aH[mi][0] = *(const unsigned*)(AsH + off);
                aH[mi][1] = *(const unsigned*)(AsH + off + 8*80);
                aH[mi][2] = *(const unsigned*)(AsH + off + 16);
                aH[mi][3] = *(const unsigned*)(AsH + off + 8*80 + 16);
                aL[mi][0] = *(const unsigned*)(AsL + off);
                aL[mi][1] = *(const unsigned*)(AsL + off + 8*80);
                aL[mi][2] = *(const unsigned*)(AsL + off + 16);
                aL[mi][3] = *(const unsigned*)(AsL + off + 8*80 + 16);
            }
            #pragma unroll
            for (int ni = 0; ni < 8; ni++) {
                int off = (wn + (ni<<3) + lq)*80 + kb;
                bH[ni][0] = *(const unsigned*)(BsH + off);
                bH[ni][1] = *(const unsigned*)(BsH + off + 16);
                bL[ni][0] = *(const unsigned*)(BsL + off);
                bL[ni][1] = *(const unsigned*)(BsL + off + 16);
            }
            #pragma unroll
            for (int mi = 0; mi < 2; mi++)
                #pragma unroll
                for (int ni = 0; ni < 8; ni++) {
                    MMA_BF16(acc[mi][ni], aH[mi][0],aH[mi][1],aH[mi][2],aH[mi][3], bH[ni][0],bH[ni][1]);
                    MMA_BF16(acc[mi][ni], aH[mi][0],aH[mi][1],aH[mi][2],aH[mi][3], bL[ni][0],bL[ni][1]);
                    MMA_BF16(acc[mi][ni], aL[mi][0],aL[mi][1],aL[mi][2],aL[mi][3], bH[ni][0],bH[ni][1]);
                }
        }
        if (ti + 2 < ntiles) {
            int nbuf = buf + 2; if (nbuf >= 3) nbuf -= 3;
            load_tile(ti + 2, nbuf);
        }
        if (++buf == 3) buf = 0;
    }
    #pragma unroll
    for (int mi = 0; mi < 2; mi++) {
        int row0 = bm + wm + (mi<<4) + lq;
        float b0 = bias[row0], b1 = bias[row0 + 8];
        #pragma unroll
        for (int ni = 0; ni < 8; ni++) {
            int col = bn + wn + (ni<<3) + (lr<<1);
            if (col < N) {
                float2 v0 = make_float2(acc[mi][ni][0] + b0, acc[mi][ni][1] + b0);
                float2 v1 = make_float2(acc[mi][ni][2] + b1, acc[mi][ni][3] + b1);
                *(float2*)&Cm[(size_t)row0 * N + col] = v0;
                *(float2*)&Cm[(size_t)(row0+8) * N + col] = v1;
            }
        }
    }
}

// ---------- fused RVQ scan: 16 warps, 4 barriers/q, redundant merge ---------
__global__ __launch_bounds__(512, 1) void rvq_scan(
    const int*   __restrict__ lens,
    const float* __restrict__ cbg,
    const float* __restrict__ qinb,
    const float* __restrict__ qoutb,
    float*       __restrict__ dout)
{
    extern __shared__ float sm[];
    float* s_res = sm;                 // 33792
    float* s_w   = s_res + 33792;      // 8192  (qout2 only)
    float* s_cb  = s_w + 8192;         // 8192
    float* s_cbn = s_cb + 8192;        // 1024
    float* s_red = s_cbn + 1024;       // 2048
    float* s_ze  = s_red + 2048;       // 256
    float* s_ob  = s_ze + 256;         // 1024
    float* s_mk  = s_ob + 1024;        // 32
    int*   s_sel = (int*)(s_mk + 32);
    int*   s_bi  = s_sel + 32;
    int*   s_ti  = s_bi + 32;
    int*   s_fl  = s_ti + 32;

    const int tid = threadIdx.x;
    const int lane = tid & 31, wrp = tid >> 5;
    const int c0 = blockIdx.x << 5;

    if (tid < 32) {
        int c = c0 + tid;
        int b = c / T_, t = c - b * T_;
        s_bi[tid] = b; s_ti[tid] = t;
        s_mk[tid] = (t < lens[b]) ? 1.f : 0.f;
    }
    __syncthreads();
    if (tid == 0) {
        float m = 0.f;
        #pragma unroll
        for (int n = 0; n < 32; n++) m += s_mk[n];
        s_fl[0] = (m == 0.f) ? 1 : 0;
    }
    __syncthreads();

    if (s_fl[0]) {
        // masked CTA: compute S locally (identical chain to old masked_S)
        __nv_bfloat16* sSH = (__nv_bfloat16*)s_res;          // 1024 bf16
        __nv_bfloat16* sSL = sSH + D_;
        for (int o = tid; o < D_; o += 512) {
            float acc = 0.f;
            for (int q = 0; q < NQ_; q++) {
                int sel = g_selm[q];
                const float* c = cbg + (size_t)q*8192 + sel*8;
                const float* w = g_qoutF + ((size_t)q*D_ + o)*8;
                float v = qoutb[(q<<10)+o];
                v = fmaf(w[0],c[0],v); v = fmaf(w[1],c[1],v);
                v = fmaf(w[2],c[2],v); v = fmaf(w[3],c[3],v);
                v = fmaf(w[4],c[4],v); v = fmaf(w[5],c[5],v);
                v = fmaf(w[6],c[6],v); v = fmaf(w[7],c[7],v);
                acc += v;
            }
            g_S[o] = acc;                       // identical redundant writes
            __nv_bfloat16 h = __float2bfloat16(acc);
            sSH[o] = h;
            sSL[o] = __float2bfloat16(acc - __bfloat162float(h));
        }
        for (int q = wrp; q < NQ_; q += 16) {
            dout[IDX_OFF + (size_t)q*NCOL + c0 + lane] = (float)g_selm[q];
            atomicAdd(&g_commit[(q<<4) + s_bi[lane]], g_csm[q]);
        }
        __syncthreads();
        for (int i = tid; i < 32*128; i += 512) {
            int n = i >> 7, j = i & 127;
            size_t base = ((size_t)s_bi[n]*T_ + s_ti[n])*D_;
            ((uint4*)(g_qTH + base))[j] = ((const uint4*)sSH)[j];
            ((uint4*)(g_qTL + base))[j] = ((const uint4*)sSL)[j];
        }
        return;
    }

    auto stage = [&](int q) {
        const float4* gc = (const float4*)(cbg + (size_t)q*8192);
        const float4* gw = (const float4*)(g_qout2 + q*8192);
        #pragma unroll
        for (int u = 0; u < 4; u++) {
            unsigned dcb = (unsigned)__cvta_generic_to_shared(&((float4*)s_cb)[tid + u*512]);
            CP16Z(dcb, gc + tid + u*512, 16);
            unsigned dw = (unsigned)__cvta_generic_to_shared(&((float4*)s_w)[tid + u*512]);
            CP16Z(dw, gw + tid + u*512, 16);
        }
        if (tid < 256) {
            unsigned dn = (unsigned)__cvta_generic_to_shared(&((float4*)s_cbn)[tid]);
            CP16Z(dn, ((const float4*)(g_cbn + q*K_)) + tid, 16);
        } else {
            int t2 = tid - 256;
            unsigned dob = (unsigned)__cvta_generic_to_shared(&((float4*)s_ob)[t2]);
            CP16Z(dob, ((const float4*)(qoutb + (q<<10))) + t2, 16);
        }
        CP_COMMIT();
    };

    stage(0);

    for (int idx = tid; idx < D_*32; idx += 512) {
        int o = idx >> 5, n = idx & 31;
        s_res[o*33+n] = g_zp[(size_t)s_bi[n]*(D_*T_) + (size_t)o*T_ + s_ti[n]];
    }
    __syncthreads();

    for (int q = 0; q < NQ_; q++) {
        { // phase B: qin2 from L2 (broadcast), bit-identical chain
            int w2 = wrp & 7, dhalf = wrp >> 3;
            const ulonglong2* qg = (const ulonglong2*)(g_qin2 + q*8192);
            unsigned long long part2[2];
            part2[0] = 0ULL; part2[1] = 0ULL;
            int ib = w2 << 7;
            for (int ii = 0; ii < 128; ii += 4) {
                float r0 = s_res[(ib+ii+0)*33+lane];
                float r1 = s_res[(ib+ii+1)*33+lane];
                float r2 = s_res[(ib+ii+2)*33+lane];
                float r3 = s_res[(ib+ii+3)*33+lane];
                unsigned long long rr0, rr1, rr2, rr3;
                PACK2(rr0, r0, r0); PACK2(rr1, r1, r1);
                PACK2(rr2, r2, r2); PACK2(rr3, r3, r3);
                #pragma unroll
                for (int jj = 0; jj < 2; jj++) {
                    int j = (dhalf<<1) + jj;
                    const ulonglong2* qp = qg + j*512 + ((ib+ii)>>1);
                    ulonglong2 qA = __ldg(qp);
                    ulonglong2 qB = __ldg(qp + 1);
                    FMA2(part2[jj], qB.y, rr3);
                    FMA2(part2[jj], qB.x, rr2);
                    FMA2(part2[jj], qA.y, rr1);
                    FMA2(part2[jj], qA.x, rr0);
                }
            }
            #pragma unroll
            for (int jj = 0; jj < 2; jj++) {
                int j = (dhalf<<1) + jj;
                unsigned lo, hi;
                UNPACK2(lo, hi, part2[jj]);
                s_red[(w2<<8)+(lane<<3)+2*j]   = __uint_as_float(lo);
                s_red[(w2<<8)+(lane<<3)+2*j+1] = __uint_as_float(hi);
            }
        }
        __syncthreads();
        if (tid < 256) { // finalize ze
            int d = tid >> 5, n = tid & 31;
            float s = 0.f;
            #pragma unroll
            for (int w2 = 0; w2 < 8; w2++) s += s_red[(w2<<8)+(n<<3)+d];
            s_ze[(n<<3)+d] = s_mk[n]*s + qinb[(q<<3)+d];
        }
        CP_WAIT0();
        __syncthreads();

        { // phase C: per-warp argmin over 64 codes (unchanged math)
            float4 za = *(float4*)&s_ze[lane<<3];
            float4 zb = *(float4*)&s_ze[(lane<<3)+4];
            float zsq = za.x*za.x+za.y*za.y+za.z*za.z+za.w*za.w
                      + zb.x*zb.x+zb.y*zb.y+zb.z*zb.z+zb.w*zb.w;
            float best = 3.402823466e38f; int bk = 0;
            int kb = wrp << 6;
            #pragma unroll 4
            for (int kk = 0; kk < 64; kk++) {
                int k = kb + kk;
                float4 ca = *(float4*)&s_cb[k<<3];
                float4 cv = *(float4*)&s_cb[(k<<3)+4];
                float dot = za.x*ca.x+za.y*ca.y+za.z*ca.z+za.w*ca.w
                          + zb.x*cv.x+zb.y*cv.y+zb.z*cv.z+zb.w*cv.w;
                float d2 = zsq - 2.f*dot + s_cbn[k];
                if (d2 < best) { best = d2; bk = k; }
            }
            s_red[(wrp<<6)+(lane<<1)]   = best;
            s_red[(wrp<<6)+(lane<<1)+1] = __int_as_float(bk);
        }
        __syncthreads();

        // phase D: all warps redundantly merge (ascending, first-min exact)
        int selk;
        {
            int n = lane;
            float best = s_red[n<<1]; int bk = __float_as_int(s_red[(n<<1)+1]);
            #pragma unroll
            for (int w2 = 1; w2 < 16; w2++) {
                float v = s_red[(w2<<6)+(n<<1)];
                if (v < best) { best = v; bk = __float_as_int(s_red[(w2<<6)+(n<<1)+1]); }
            }
            selk = bk;
            if (wrp == 0) {
                dout[IDX_OFF + (size_t)q*NCOL + c0 + n] = (float)bk;
                float cs = 0.f;
                #pragma unroll
                for (int d = 0; d < 8; d++) {
                    float dz = s_ze[(n<<3)+d] - s_cb[(bk<<3)+d];
                    cs = fmaf(dz, dz, cs);
                }
                atomicAdd(&g_commit[(q<<4) + s_bi[n]], cs);
            }
        }

        { // phase E: FFMA2 over (o,o+8) pairs (unchanged chain), sel from regs
            int n = lane;
            int ob = wrp & 7, mhalf = wrp >> 3;
            float4 ca = *(float4*)&s_cb[selk<<3];
            float4 cv = *(float4*)&s_cb[(selk<<3)+4];
            unsigned long long cc[8];
            PACK2(cc[0], ca.x, ca.x); PACK2(cc[1], ca.y, ca.y);
            PACK2(cc[2], ca.z, ca.z); PACK2(cc[3], ca.w, ca.w);
            PACK2(cc[4], cv.x, cv.x); PACK2(cc[5], cv.y, cv.y);
            PACK2(cc[6], cv.z, cv.z); PACK2(cc[7], cv.w, cv.w);
            #pragma unroll 4
            for (int mm = 0; mm < 32; mm++) {
                int m = (mhalf << 5) + mm;
                const float* wp = &s_w[(m*8 + ob)*16];
                ulonglong2 w01 = *(const ulonglong2*)(wp);
                ulonglong2 w23 = *(const ulonglong2*)(wp + 4);
                ulonglong2 w45 = *(const ulonglong2*)(wp + 8);
                ulonglong2 w67 = *(const ulonglong2*)(wp + 12);
                int o = (m << 4) + ob;
                unsigned long long v2;
                PACK2(v2, s_ob[o], s_ob[o+8]);
                FMA2(v2, w01.x, cc[0]); FMA2(v2, w01.y, cc[1]);
                FMA2(v2, w23.x, cc[2]); FMA2(v2, w23.y, cc[3]);
                FMA2(v2, w45.x, cc[4]); FMA2(v2, w45.y, cc[5]);
                FMA2(v2, w67.x, cc[6]); FMA2(v2, w67.y, cc[7]);
                unsigned lo, hi;
                UNPACK2(lo, hi, v2);
                s_res[o*33+n]     -= __uint_as_float(lo);
                s_res[(o+8)*33+n] -= __uint_as_float(hi);
            }
        }
        __syncthreads();
        if (q + 1 < NQ_) stage(q + 1);
    }

    for (int idx = tid; idx < D_*32; idx += 512) {
        int o = idx >> 5, n = idx & 31;
        size_t ga = (size_t)s_bi[n]*(D_*T_) + (size_t)o*T_ + s_ti[n];
        s_res[o*33+n] = g_zp[ga] - s_res[o*33+n];
    }
    __syncthreads();
    for (int idx = tid; idx < D_*32; idx += 512) {
        int n = idx >> 10, o = idx & 1023;
        float v = s_res[o*33+n];
        __nv_bfloat16 h = __float2bfloat16(v);
        size_t a = ((size_t)s_bi[n]*T_ + s_ti[n])*D_ + o;
        g_qTH[a] = h;
        g_qTL[a] = __float2bfloat16(v - __bfloat162float(h));
    }
}

extern "C" void kernel_launch(void* const* d_in, const int* in_sizes, int n_in,
                              void* d_out, int out_size) {
    const float* z          = (const float*)d_in[0];
    const int*   lens       = (const int*)d_in[1];
    const float* in_proj_v  = (const float*)d_in[2];
    const float* in_proj_g  = (const float*)d_in[3];
    const float* in_proj_b  = (const float*)d_in[4];
    const float* out_proj_v = (const float*)d_in[5];
    const float* out_proj_g = (const float*)d_in[6];
    const float* out_proj_b = (const float*)d_in[7];
    const float* q_in_v     = (const float*)d_in[8];
    const float* q_in_g     = (const float*)d_in[9];
    const float* q_in_b     = (const float*)d_in[10];
    const float* q_out_v    = (const float*)d_in[11];
    const float* q_out_g    = (const float*)d_in[12];
    const float* q_out_b    = (const float*)d_in[13];
    const float* codebooks  = (const float*)d_in[14];
    float* dout = (float*)d_out;

    void *pWinT, *pWoutH, *pWoutL, *pzp, *pqTH, *pqTL;
    cudaGetSymbolAddress(&pWinT,  g_WinT);
    cudaGetSymbolAddress(&pWoutH, g_WoutH);
    cudaGetSymbolAddress(&pWoutL, g_WoutL);
    cudaGetSymbolAddress(&pzp,    g_zp);
    cudaGetSymbolAddress(&pqTH,   g_qTH);
    cudaGetSymbolAddress(&pqTL,   g_qTL);

    cudaFuncSetAttribute(rvq_scan,   cudaFuncAttributeMaxDynamicSharedMemorySize, 218656);
    cudaFuncSetAttribute(gemm_bf16x2, cudaFuncAttributeMaxDynamicSharedMemorySize, 122880);
    cudaFuncSetAttribute(sgemm256,   cudaFuncAttributeMaxDynamicSharedMemorySize, 73728);

    // rvq_scan is the 4th launch -> profiled
    prep_all<<<4368, 32>>>(in_proj_v, in_proj_g, out_proj_v, out_proj_g,
                           q_in_v, q_in_g, q_out_v, q_out_g, codebooks);
    masked_sel<<<NQ_, 256>>>(q_in_b, codebooks);

    sgemm256<<<dim3((T_+255)/256, D_/128, B_), 256, 73728>>>(
        (const float*)pWinT, z, in_proj_b, (float*)pzp, lens,
        T_, DIN, D_, (size_t)DIN*T_, (size_t)D_*T_);

    rvq_scan<<<NCOL/32, 512, 218656>>>(lens, codebooks, q_in_b, q_out_b, dout);

    gemv_S<<<D_, 32>>>(out_proj_b);
    commit_fin<<<1, 512>>>(dout);

    gemm_bf16x2<<<dim3((T_+127)/128, D_/128, B_), 256, 122880>>>(
        (const __nv_bfloat16*)pWoutH, (const __nv_bfloat16*)pWoutL,
        (const __nv_bfloat16*)pqTH, (const __nv_bfloat16*)pqTL,
        out_proj_b, dout, lens, T_, D_, (size_t)T_*D_, (size_t)D_*T_);
}

// round 16
// speedup vs baseline: 1.2110x; 1.0492x over previous
#include <cuda_runtime.h>
#include <cuda_bf16.h>
#include <math.h>

#define B_   16
#define T_   2000
#define DIN  1280
#define D_   1024
#define NQ_  32
#define K_   1024
#define NCOL (B_*T_)
#define OUT_ELEMS ((size_t)B_*D_*T_)
#define IDX_OFF   OUT_ELEMS
#define COMMIT_OFF (OUT_ELEMS + (size_t)NQ_*NCOL)

__device__ float g_WinT[DIN*D_];
__device__ __nv_bfloat16 g_WoutH[D_*D_];
__device__ __nv_bfloat16 g_WoutL[D_*D_];
__device__ float g_WoutF[D_*D_];
__device__ float g_qin2 [NQ_*8*D_];
__device__ float g_qout2[NQ_*D_*8];     // [q][d][p][2], pair (o, o+32), p = (o>>6)*32 + (o&31)
__device__ float g_qoutF[NQ_*D_*8];
__device__ float g_cbn [NQ_*K_];
__device__ float g_zp  [(size_t)B_*D_*T_];
__device__ __align__(16) __nv_bfloat16 g_qTH[(size_t)B_*T_*D_];
__device__ __align__(16) __nv_bfloat16 g_qTL[(size_t)B_*T_*D_];
__device__ int   g_selm[NQ_];
__device__ float g_csm [NQ_];
__device__ float g_S   [D_];
__device__ float g_outS[D_];
__device__ float g_commit[NQ_*B_];

#define CP16Z(dst, src, p) asm volatile("cp.async.cg.shared.global [%0], [%1], 16, %2;\n" :: "r"(dst), "l"(src), "r"(p))
#define CP_COMMIT() asm volatile("cp.async.commit_group;\n")
#define CP_WAIT1() asm volatile("cp.async.wait_group 1;\n")
#define CP_WAIT0() asm volatile("cp.async.wait_group 0;\n")

#define MMA_BF16(d, a0,a1,a2,a3, b0,b1) \
    asm volatile("mma.sync.aligned.m16n8k16.row.col.f32.bf16.bf16.f32 " \
        "{%0,%1,%2,%3},{%4,%5,%6,%7},{%8,%9},{%0,%1,%2,%3};\n" \
        : "+f"(d[0]),"+f"(d[1]),"+f"(d[2]),"+f"(d[3]) \
        : "r"(a0),"r"(a1),"r"(a2),"r"(a3),"r"(b0),"r"(b1))

#define PACK2(o, lo, hi) \
    asm("mov.b64 %0, {%1, %2};" : "=l"(o) : "r"(__float_as_uint(lo)), "r"(__float_as_uint(hi)))
#define FMA2(acc, a, b) \
    asm("fma.rn.f32x2 %0, %1, %2, %0;" : "+l"(acc) : "l"(a), "l"(b))
#define UNPACK2(lo, hi, in) \
    asm("mov.b64 {%0, %1}, %2;" : "=r"(lo), "=r"(hi) : "l"(in))

// ---------------- fused prep ------------------------------------------------
__global__ void prep_all(const float* __restrict__ in_v,  const float* __restrict__ in_g,
                         const float* __restrict__ out_v, const float* __restrict__ out_g,
                         const float* __restrict__ qi_v,  const float* __restrict__ qi_g,
                         const float* __restrict__ qo_v,  const float* __restrict__ qo_g,
                         const float* __restrict__ cb) {
    int blk = blockIdx.x, t = threadIdx.x;
    if (blk < 1024) {
        int row = blk;
        const float* vr = in_v + (size_t)row * DIN;
        float s = 0.f;
        for (int i = t; i < DIN; i += 32) { float x = vr[i]; s = fmaf(x,x,s); }
        #pragma unroll
        for (int o = 16; o; o >>= 1) s += __shfl_xor_sync(0xffffffffu, s, o);
        float sc = in_g[row] / sqrtf(s);
        for (int i = t; i < DIN; i += 32) g_WinT[(size_t)i*D_ + row] = vr[i] * sc;
    } else if (blk < 2048) {
        int row = blk - 1024;
        const float* vr = out_v + (size_t)row * D_;
        float s = 0.f;
        for (int i = t; i < D_; i += 32) { float x = vr[i]; s = fmaf(x,x,s); }
        #pragma unroll
        for (int o = 16; o; o >>= 1) s += __shfl_xor_sync(0xffffffffu, s, o);
        float sc = out_g[row] / sqrtf(s);
        for (int i = t; i < D_; i += 32) {
            float w = vr[i] * sc;
            g_WoutF[(size_t)row*D_ + i] = w;
            __nv_bfloat16 h = __float2bfloat16(w);
            g_WoutH[(size_t)row*D_ + i] = h;
            g_WoutL[(size_t)row*D_ + i] = __float2bfloat16(w - __bfloat162float(h));
        }
    } else if (blk < 2304) {
        int row = blk - 2048; int q = row >> 3, d = row & 7;
        const float* vr = qi_v + (size_t)row * D_;
        float s = 0.f;
        for (int i = t; i < D_; i += 32) { float x = vr[i]; s = fmaf(x,x,s); }
        #pragma unroll
        for (int o = 16; o; o >>= 1) s += __shfl_xor_sync(0xffffffffu, s, o);
        float sc = qi_g[row] / sqrtf(s);
        float* ob = g_qin2 + q*8192 + (d>>1)*2048 + (d&1);
        for (int i = t; i < D_; i += 32) ob[i*2] = vr[i] * sc;
    } else if (blk < 3328) {
        int row = (blk - 2304)*32 + t;
        int q = row >> 10, o = row & 1023;
        const float* vr = qo_v + (size_t)row * 8;
        float x0=vr[0]*vr[0], x1=vr[1]*vr[1], x2=vr[2]*vr[2], x3=vr[3]*vr[3];
        float x4=vr[4]*vr[4], x5=vr[5]*vr[5], x6=vr[6]*vr[6], x7=vr[7]*vr[7];
        float s = ((x0+x4)+(x2+x6)) + ((x1+x5)+(x3+x7));
        float sc = qo_g[row] / sqrtf(s);
        float* pf = g_qoutF + (size_t)row * 8;
        int oo = o & 63;
        int slot = oo >> 5;
        int p = (o >> 6) * 32 + (oo & 31);
        float* pp = g_qout2 + q*8192 + p*2 + slot;
        #pragma unroll
        for (int d = 0; d < 8; d++) { float w = vr[d]*sc; pf[d] = w; pp[d*1024] = w; }
    } else if (blk < 4352) {
        int i = (blk - 3328)*32 + t;
        const float* c = cb + (size_t)i * 8;
        float s = 0.f;
        #pragma unroll
        for (int d = 0; d < 8; d++) s = fmaf(c[d], c[d], s);
        g_cbn[i] = s;
    } else {
        int i = (blk - 4352)*32 + t;
        if (i < NQ_*B_) g_commit[i] = 0.f;
    }
}

// ---- masked constants ------------------------------------------------------
__global__ void masked_sel(const float* __restrict__ qinb,
                           const float* __restrict__ cbg) {
    __shared__ float sv[256];
    __shared__ int   si[256];
    int q = blockIdx.x, tid = threadIdx.x;
    float ze[8];
    #pragma unroll
    for (int d = 0; d < 8; d++) ze[d] = qinb[(q<<3)+d];
    float zsq = 0.f;
    #pragma unroll
    for (int d = 0; d < 8; d++) zsq += ze[d]*ze[d];
    const float* cbq = cbg + (size_t)q*8192;
    float best = 3.402823466e38f; int bk = 0;
    #pragma unroll
    for (int kk = 0; kk < 4; kk++) {
        int k = tid*4 + kk;
        const float* c = cbq + k*8;
        float dot = 0.f;
        #pragma unroll
        for (int d = 0; d < 8; d++) dot += ze[d]*c[d];
        float cbn = 0.f;
        #pragma unroll
        for (int d = 0; d < 8; d++) cbn = fmaf(c[d], c[d], cbn);
        float d2 = zsq - 2.f*dot + cbn;
        if (d2 < best) { best = d2; bk = k; }
    }
    sv[tid] = best; si[tid] = bk;
    __syncthreads();
    for (int s = 128; s; s >>= 1) {
        if (tid < s && sv[tid+s] < sv[tid]) { sv[tid] = sv[tid+s]; si[tid] = si[tid+s]; }
        __syncthreads();
    }
    if (tid == 0) {
        int s = si[0];
        g_selm[q] = s;
        const float* c = cbq + s*8;
        float cs = 0.f;
        #pragma unroll
        for (int d = 0; d < 8; d++) { float dz = ze[d]-c[d]; cs = fmaf(dz,dz,cs); }
        g_csm[q] = cs;
    }
}

__global__ void commit_fin(float* __restrict__ dout) {
    if (threadIdx.x < NQ_*B_)
        dout[COMMIT_OFF + threadIdx.x] = g_commit[threadIdx.x] * (1.0f / (float)(T_*8));
}

__global__ void gemv_S(const float* __restrict__ bias) {
    int o = blockIdx.x;
    const float* w = g_WoutF + (size_t)o * D_;
    float acc = 0.f;
    for (int i = threadIdx.x; i < D_; i += 32) acc = fmaf(w[i], g_S[i], acc);
    #pragma unroll
    for (int off = 16; off; off >>= 1) acc += __shfl_xor_sync(0xffffffffu, acc, off);
    if (threadIdx.x == 0) g_outS[o] = acc + bias[o];
}

// ---- fp32 SGEMM, 128x256 tile, FFMA2, 3-stage cp.async pipeline ------------
__global__ __launch_bounds__(256, 1) void sgemm256(
    const float* __restrict__ AT, const float* __restrict__ B0,
    const float* __restrict__ bias, float* __restrict__ C0,
    const int* __restrict__ lens,
    int N, int Kd, int Mtot, size_t strideB, size_t strideC)
{
    extern __shared__ float smem[];
    const float* Bm = B0 + (size_t)blockIdx.z * strideB;
    float* Cm = C0 + (size_t)blockIdx.z * strideC;
    int bm = blockIdx.y << 7, bn = blockIdx.x << 8;
    int tid = threadIdx.x;

    if (bn >= lens[blockIdx.z]) {
        float4 zz = make_float4(0.f,0.f,0.f,0.f);
        #pragma unroll
        for (int u = 0; u < 32; u++) {
            int i = tid + u*256;
            int r = i >> 6, c4 = (i & 63) * 4;
            int col = bn + c4;
            if (col < N) *(float4*)&Cm[(size_t)(bm + r) * N + col] = zz;
        }
        return;
    }

    int tx = tid & 15, ty = tid >> 4;
    unsigned long long acc2[8][8];
    #pragma unroll
    for (int i = 0; i < 8; i++)
        #pragma unroll
        for (int j = 0; j < 8; j++) acc2[i][j] = 0ULL;

    auto load_tile = [&](int k0, int buf) {
        float* As = smem + buf * 6144;
        float* Bs = As + 2048;
        #pragma unroll
        for (int u = 0; u < 2; u++) {
            int i = tid + u*256;
            int r = i >> 5, c = (i & 31) * 4;
            unsigned d = (unsigned)__cvta_generic_to_shared(As + r*128 + c);
            CP16Z(d, AT + (size_t)(k0 + r)*Mtot + bm + c, 16);
        }
        #pragma unroll
        for (int u = 0; u < 4; u++) {
            int i = tid + u*256;
            int r = i >> 6, c = (i & 63) * 4;
            int col = bn + c;
            int p = 16;
            if (col >= N) { col = 0; p = 0; }
            unsigned d = (unsigned)__cvta_generic_to_shared(Bs + r*256 + c);
            CP16Z(d, Bm + (size_t)(k0 + r)*N + col, p);
        }
        CP_COMMIT();
    };

    int ntiles = Kd >> 4;
    load_tile(0, 0);
    load_tile(16, 1);
    int buf = 0;
    for (int ti = 0; ti < ntiles; ti++) {
        if (ti + 1 < ntiles) CP_WAIT1(); else CP_WAIT0();
        __syncthreads();
        const float* As = smem + buf * 6144;
        const float* Bs = As + 2048;
        #pragma unroll
        for (int kk = 0; kk < 16; kk++) {
            float af[8], bf[16];
            *(float4*)&af[0] = *(const float4*)&As[kk*128 + ty*8];
            *(float4*)&af[4] = *(const float4*)&As[kk*128 + ty*8 + 4];
            #pragma unroll
            for (int c = 0; c < 4; c++)
                *(float4*)&bf[c*4] = *(const float4*)&Bs[kk*256 + c*64 + tx*4];
            unsigned long long bb[8];
            #pragma unroll
            for (int j = 0; j < 8; j++) PACK2(bb[j], bf[2*j], bf[2*j+1]);
            #pragma unroll
            for (int i = 0; i < 8; i++) {
                unsigned long long aa;
                PACK2(aa, af[i], af[i]);
                #pragma unroll
                for (int j = 0; j < 8; j++) FMA2(acc2[i][j], aa, bb[j]);
            }
        }
        if (ti + 2 < ntiles) {
            int nbuf = buf + 2; if (nbuf >= 3) nbuf -= 3;
            load_tile((ti+2) << 4, nbuf);
        }
        if (++buf == 3) buf = 0;
    }
    #pragma unroll
    for (int i = 0; i < 8; i++) {
        int row = bm + ty*8 + i;
        float bv = bias[row];
        #pragma unroll
        for (int c = 0; c < 4; c++) {
            int col = bn + c*64 + tx*4;
            if (col < N) {
                unsigned l0, h0, l1, h1;
                UNPACK2(l0, h0, acc2[i][2*c]);
                UNPACK2(l1, h1, acc2[i][2*c+1]);
                float4 o;
                o.x = __uint_as_float(l0) + bv;
                o.y = __uint_as_float(h0) + bv;
                o.z = __uint_as_float(l1) + bv;
                o.w = __uint_as_float(h1) + bv;
                *(float4*)&Cm[(size_t)row * N + col] = o;
            }
        }
    }
}

// ------- bf16x2-split GEMM (3 products), 3-stage pipeline -------------------
__global__ __launch_bounds__(256, 1) void gemm_bf16x2(
    const __nv_bfloat16* __restrict__ AH, const __nv_bfloat16* __restrict__ AL,
    const __nv_bfloat16* __restrict__ BH0, const __nv_bfloat16* __restrict__ BL0,
    const float* __restrict__ bias, float* __restrict__ C0,
    const int* __restrict__ lens,
    int N, int Kd, size_t sB, size_t sC)
{
    extern __shared__ __align__(16) unsigned char sb[];
    const __nv_bfloat16* BH = BH0 + (size_t)blockIdx.z * sB;
    const __nv_bfloat16* BL = BL0 + (size_t)blockIdx.z * sB;
    float* Cm = C0 + (size_t)blockIdx.z * sC;
    int bm = blockIdx.y << 7, bn = blockIdx.x << 7;
    int tid = threadIdx.x, lane = tid & 31, wid = tid >> 5;

    if (bn >= lens[blockIdx.z]) {
        const float* oS = g_outS + bm;
        #pragma unroll
        for (int u = 0; u < 16; u++) {
            int i = tid + u*256;
            int r = i >> 5, c4 = (i & 31) * 4;
            int col = bn + c4;
            float v = oS[r];
            if (col < N) *(float4*)&Cm[(size_t)(bm + r) * N + col] = make_float4(v,v,v,v);
        }
        return;
    }

    int wm = (wid & 3) << 5, wn = (wid >> 2) << 6;
    int lq = lane >> 2, lr = lane & 3;
    int ntiles = Kd >> 5;

    float acc[2][8][4];
    #pragma unroll
    for (int mi = 0; mi < 2; mi++)
        #pragma unroll
        for (int ni = 0; ni < 8; ni++)
            #pragma unroll
            for (int c = 0; c < 4; c++) acc[mi][ni][c] = 0.f;

    auto load_tile = [&](int ti, int buf) {
        unsigned char* base = sb + buf * 40960;
        int k0 = ti << 5;
        #pragma unroll
        for (int r = 0; r < 8; r++) {
            int idx = r*256 + tid;
            int region = idx >> 9, w = idx & 511;
            int row = w >> 2, ch = w & 3;
            unsigned daddr = (unsigned)__cvta_generic_to_shared(base + region*10240 + row*80 + ch*16);
            const __nv_bfloat16* src; int p = 16;
            if (region == 0)      src = AH + (size_t)(bm+row)*Kd + k0 + ch*8;
            else if (region == 1) src = AL + (size_t)(bm+row)*Kd + k0 + ch*8;
            else {
                int gr = bn + row; if (gr >= N) { gr = 0; p = 0; }
                src = (region == 2 ? BH : BL) + (size_t)gr*Kd + k0 + ch*8;
            }
            CP16Z(daddr, src, p);
        }
        CP_COMMIT();
    };

    load_tile(0, 0);
    load_tile(1, 1);
    int buf = 0;
    for (int ti = 0; ti < ntiles; ti++) {
        if (ti + 1 < ntiles) CP_WAIT1(); else CP_WAIT0();
        __syncthreads();
        const unsigned char* base = sb + buf * 40960;
        const unsigned char* AsH = base;
        const unsigned char* AsL = base + 10240;
        const unsigned char* BsH = base + 20480;
        const unsigned char* BsL = base + 30720;
        #pragma unroll
        for (int ks = 0; ks < 2; ks++) {
            int kb = ks*32 + lr*4;
            unsigned aH[2][4], aL[2][4], bH[8][2], bL[8][2];
            #pragma unroll
            for (int mi = 0; mi < 2; mi++) {
                int off = (wm + (mi<<4) + lq)*80 + kb;
                aH[mi][0] = *(const unsigned*)(AsH + off);
                aH[mi][1] = *(const unsigned*)(AsH + off + 8*80);
                aH[mi][2] = *(const unsigned*)(AsH + off + 16);
                aH[mi][3] = *(const unsigned*)(AsH + off + 8*80 + 16);
                aL[mi][0] = *(const unsigned*)(AsL + off);
                aL[mi][1] = *(const unsigned*)(AsL + off + 8*80);
                aL[mi][2] = *(const unsigned*)(AsL + off + 16);
                aL[mi][3] = *(const unsigned*)(AsL + off + 8*80 + 16);
            }
            #pragma unroll
            for (int ni = 0; ni < 8; ni++) {
                int off = (wn + (ni<<3) + lq)*80 + kb;
                bH[ni][0] = *(const unsigned*)(BsH + off);
                bH[ni][1] = *(const unsigned*)(BsH + off + 16);
                bL[ni][0] = *(const unsigned*)(BsL + off);
                bL[ni][1] = *(const unsigned*)(BsL + off + 16);
            }
            #pragma unroll
            for (int mi = 0; mi < 2; mi++)
                #pragma unroll
                for (int ni = 0; ni < 8; ni++) {
                    MMA_BF16(acc[mi][ni], aH[mi][0],aH[mi][1],aH[mi][2],aH[mi][3], bH[ni][0],bH[ni][1]);
                    MMA_BF16(acc[mi][ni], aH[mi][0],aH[mi][1],aH[mi][2],aH[mi][3], bL[ni][0],bL[ni][1]);
                    MMA_BF16(acc[mi][ni], aL[mi][0],aL[mi][1],aL[mi][2],aL[mi][3], bH[ni][0],bH[ni][1]);
                }
        }
        if (ti + 2 < ntiles) {
            int nbuf = buf + 2; if (nbuf >= 3) nbuf -= 3;
            load_tile(ti + 2, nbuf);
        }
        if (++buf == 3) buf = 0;
    }
    #pragma unroll
    for (int mi = 0; mi < 2; mi++) {
        int row0 = bm + wm + (mi<<4) + lq;
        float b0 = bias[row0], b1 = bias[row0 + 8];
        #pragma unroll
        for (int ni = 0; ni < 8; ni++) {
            int col = bn + wn + (ni<<3) + (lr<<1);
            if (col < N) {
                float2 v0 = make_float2(acc[mi][ni][0] + b0, acc[mi][ni][1] + b0);
                float2 v1 = make_float2(acc[mi][ni][2] + b1, acc[mi][ni][3] + b1);
                *(float2*)&Cm[(size_t)row0 * N + col] = v0;
                *(float2*)&Cm[(size_t)(row0+8) * N + col] = v1;
            }
        }
    }
}

// ---------- fused RVQ scan: 16 warps, o-major phase E ------------------------
__global__ __launch_bounds__(512, 1) void rvq_scan(
    const int*   __restrict__ lens,
    const float* __restrict__ cbg,
    const float* __restrict__ qinb,
    const float* __restrict__ qoutb,
    float*       __restrict__ dout)
{
    extern __shared__ float sm[];
    float* s_res = sm;                 // 33792
    float* s_w   = s_res + 33792;      // 8192 (qout2 [d][p][2])
    float* s_cb  = s_w + 8192;         // 8192
    float* s_cbn = s_cb + 8192;        // 1024
    float* s_red = s_cbn + 1024;       // 2048
    float* s_ze  = s_red + 2048;       // 256
    float* s_ob  = s_ze + 256;         // 1024
    float* s_mk  = s_ob + 1024;        // 32
    int*   s_bi  = (int*)(s_mk + 32);
    int*   s_ti  = s_bi + 32;
    int*   s_fl  = s_ti + 32;

    const int tid = threadIdx.x;
    const int lane = tid & 31, wrp = tid >> 5;
    const int c0 = blockIdx.x << 5;

    if (tid < 32) {
        int c = c0 + tid;
        int b = c / T_, t = c - b * T_;
        s_bi[tid] = b; s_ti[tid] = t;
        s_mk[tid] = (t < lens[b]) ? 1.f : 0.f;
    }
    __syncthreads();
    if (tid == 0) {
        float m = 0.f;
        #pragma unroll
        for (int n = 0; n < 32; n++) m += s_mk[n];
        s_fl[0] = (m == 0.f) ? 1 : 0;
    }
    __syncthreads();

    if (s_fl[0]) {
        __nv_bfloat16* sSH = (__nv_bfloat16*)s_res;
        __nv_bfloat16* sSL = sSH + D_;
        for (int o = tid; o < D_; o += 512) {
            float acc = 0.f;
            for (int q = 0; q < NQ_; q++) {
                int sel = g_selm[q];
                const float* c = cbg + (size_t)q*8192 + sel*8;
                const float* w = g_qoutF + ((size_t)q*D_ + o)*8;
                float v = qoutb[(q<<10)+o];
                v = fmaf(w[0],c[0],v); v = fmaf(w[1],c[1],v);
                v = fmaf(w[2],c[2],v); v = fmaf(w[3],c[3],v);
                v = fmaf(w[4],c[4],v); v = fmaf(w[5],c[5],v);
                v = fmaf(w[6],c[6],v); v = fmaf(w[7],c[7],v);
                acc += v;
            }
            g_S[o] = acc;
            __nv_bfloat16 h = __float2bfloat16(acc);
            sSH[o] = h;
            sSL[o] = __float2bfloat16(acc - __bfloat162float(h));
        }
        for (int q = wrp; q < NQ_; q += 16) {
            dout[IDX_OFF + (size_t)q*NCOL + c0 + lane] = (float)g_selm[q];
            atomicAdd(&g_commit[(q<<4) + s_bi[lane]], g_csm[q]);
        }
        __syncthreads();
        for (int i = tid; i < 32*128; i += 512) {
            int n = i >> 7, j = i & 127;
            size_t base = ((size_t)s_bi[n]*T_ + s_ti[n])*D_;
            ((uint4*)(g_qTH + base))[j] = ((const uint4*)sSH)[j];
            ((uint4*)(g_qTL + base))[j] = ((const uint4*)sSL)[j];
        }
        return;
    }

    auto stage = [&](int q) {
        const float4* gc = (const float4*)(cbg + (size_t)q*8192);
        const float4* gw = (const float4*)(g_qout2 + q*8192);
        #pragma unroll
        for (int u = 0; u < 4; u++) {
            unsigned dcb = (unsigned)__cvta_generic_to_shared(&((float4*)s_cb)[tid + u*512]);
            CP16Z(dcb, gc + tid + u*512, 16);
            unsigned dw = (unsigned)__cvta_generic_to_shared(&((float4*)s_w)[tid + u*512]);
            CP16Z(dw, gw + tid + u*512, 16);
        }
        if (tid < 256) {
            unsigned dn = (unsigned)__cvta_generic_to_shared(&((float4*)s_cbn)[tid]);
            CP16Z(dn, ((const float4*)(g_cbn + q*K_)) + tid, 16);
        } else {
            int t2 = tid - 256;
            unsigned dob = (unsigned)__cvta_generic_to_shared(&((float4*)s_ob)[t2]);
            CP16Z(dob, ((const float4*)(qoutb + (q<<10))) + t2, 16);
        }
        CP_COMMIT();
    };

    stage(0);

    for (int idx = tid; idx < D_*32; idx += 512) {
        int o = idx >> 5, n = idx & 31;
        s_res[o*33+n] = g_zp[(size_t)s_bi[n]*(D_*T_) + (size_t)o*T_ + s_ti[n]];
    }
    __syncthreads();

    for (int q = 0; q < NQ_; q++) {
        { // phase B: qin2 from L2 (broadcast), bit-identical chain
            int w2 = wrp & 7, dhalf = wrp >> 3;
            const ulonglong2* qg = (const ulonglong2*)(g_qin2 + q*8192);
            unsigned long long part2[2];
            part2[0] = 0ULL; part2[1] = 0ULL;
            int ib = w2 << 7;
            for (int ii = 0; ii < 128; ii += 4) {
                float r0 = s_res[(ib+ii+0)*33+lane];
                float r1 = s_res[(ib+ii+1)*33+lane];
                float r2 = s_res[(ib+ii+2)*33+lane];
                float r3 = s_res[(ib+ii+3)*33+lane];
                unsigned long long rr0, rr1, rr2, rr3;
                PACK2(rr0, r0, r0); PACK2(rr1, r1, r1);
                PACK2(rr2, r2, r2); PACK2(rr3, r3, r3);
                #pragma unroll
                for (int jj = 0; jj < 2; jj++) {
                    int j = (dhalf<<1) + jj;
                    const ulonglong2* qp = qg + j*512 + ((ib+ii)>>1);
                    ulonglong2 qA = __ldg(qp);
                    ulonglong2 qB = __ldg(qp + 1);
                    FMA2(part2[jj], qB.y, rr3);
                    FMA2(part2[jj], qB.x, rr2);
                    FMA2(part2[jj], qA.y, rr1);
                    FMA2(part2[jj], qA.x, rr0);
                }
            }
            #pragma unroll
            for (int jj = 0; jj < 2; jj++) {
                int j = (dhalf<<1) + jj;
                unsigned lo, hi;
                UNPACK2(lo, hi, part2[jj]);
                s_red[(w2<<8)+(lane<<3)+2*j]   = __uint_as_float(lo);
                s_red[(w2<<8)+(lane<<3)+2*j+1] = __uint_as_float(hi);
            }
        }
        __syncthreads();
        if (tid < 256) { // finalize ze
            int d = tid >> 5, n = tid & 31;
            float s = 0.f;
            #pragma unroll
            for (int w2 = 0; w2 < 8; w2++) s += s_red[(w2<<8)+(n<<3)+d];
            s_ze[(n<<3)+d] = s_mk[n]*s + qinb[(q<<3)+d];
        }
        CP_WAIT0();
        __syncthreads();

        { // phase C: per-warp argmin over 64 codes (math unchanged, cbn via float4)
            float4 za = *(float4*)&s_ze[lane<<3];
            float4 zb = *(float4*)&s_ze[(lane<<3)+4];
            float zsq = za.x*za.x+za.y*za.y+za.z*za.z+za.w*za.w
                      + zb.x*zb.x+zb.y*zb.y+zb.z*zb.z+zb.w*zb.w;
            float best = 3.402823466e38f; int bk = 0;
            int kb = wrp << 6;
            #pragma unroll 2
            for (int k4 = 0; k4 < 16; k4++) {
                float4 cb4 = *(float4*)&s_cbn[kb + k4*4];
                float cn[4] = {cb4.x, cb4.y, cb4.z, cb4.w};
                #pragma unroll
                for (int j = 0; j < 4; j++) {
                    int k = kb + k4*4 + j;
                    float4 ca = *(float4*)&s_cb[k<<3];
                    float4 cv = *(float4*)&s_cb[(k<<3)+4];
                    float dot = za.x*ca.x+za.y*ca.y+za.z*ca.z+za.w*ca.w
                              + zb.x*cv.x+zb.y*cv.y+zb.z*cv.z+zb.w*cv.w;
                    float d2 = zsq - 2.f*dot + cn[j];
                    if (d2 < best) { best = d2; bk = k; }
                }
            }
            s_red[(wrp<<6)+(lane<<1)]   = best;
            s_red[(wrp<<6)+(lane<<1)+1] = __int_as_float(bk);
        }
        __syncthreads();

        // phase D: all warps redundantly merge (ascending, first-min exact)
        int selk;
        {
            int n = lane;
            float best = s_red[n<<1]; int bk = __float_as_int(s_red[(n<<1)+1]);
            #pragma unroll
            for (int w2 = 1; w2 < 16; w2++) {
                float v = s_red[(w2<<6)+(n<<1)];
                if (v < best) { best = v; bk = __float_as_int(s_red[(w2<<6)+(n<<1)+1]); }
            }
            selk = bk;
            if (wrp == 0) {
                dout[IDX_OFF + (size_t)q*NCOL + c0 + n] = (float)bk;
                float cs = 0.f;
                #pragma unroll
                for (int d = 0; d < 8; d++) {
                    float dz = s_ze[(n<<3)+d] - s_cb[(bk<<3)+d];
                    cs = fmaf(dz, dz, cs);
                }
                atomicAdd(&g_commit[(q<<4) + s_bi[n]], cs);
            }
        }

        { // phase E (o-major): lane owns pair (o1, o1+32); loop over columns n
            int p = (wrp << 5) + lane;          // pair index
            int o1 = (wrp << 6) + lane;         // o2 = o1 + 32
            unsigned long long wd[8];
            #pragma unroll
            for (int d = 0; d < 8; d++)
                wd[d] = *(const unsigned long long*)&s_w[d*1024 + p*2];
            unsigned long long obp;
            PACK2(obp, s_ob[o1], s_ob[o1 + 32]);
            float* r1 = &s_res[o1*33];
            float* r2 = &s_res[(o1+32)*33];
            #pragma unroll 4
            for (int n = 0; n < 32; n++) {
                int sel = __shfl_sync(0xffffffffu, selk, n);
                float4 ca = *(float4*)&s_cb[sel<<3];
                float4 cv = *(float4*)&s_cb[(sel<<3)+4];
                unsigned long long v2 = obp;
                unsigned long long cc;
                PACK2(cc, ca.x, ca.x); FMA2(v2, wd[0], cc);
                PACK2(cc, ca.y, ca.y); FMA2(v2, wd[1], cc);
                PACK2(cc, ca.z, ca.z); FMA2(v2, wd[2], cc);
                PACK2(cc, ca.w, ca.w); FMA2(v2, wd[3], cc);
                PACK2(cc, cv.x, cv.x); FMA2(v2, wd[4], cc);
                PACK2(cc, cv.y, cv.y); FMA2(v2, wd[5], cc);
                PACK2(cc, cv.z, cv.z); FMA2(v2, wd[6], cc);
                PACK2(cc, cv.w, cv.w); FMA2(v2, wd[7], cc);
                unsigned lo, hi;
                UNPACK2(lo, hi, v2);
                r1[n] -= __uint_as_float(lo);
                r2[n] -= __uint_as_float(hi);
            }
        }
        __syncthreads();
        if (q + 1 < NQ_) stage(q + 1);
    }

    for (int idx = tid; idx < D_*32; idx += 512) {
        int o = idx >> 5, n = idx & 31;
        size_t ga = (size_t)s_bi[n]*(D_*T_) + (size_t)o*T_ + s_ti[n];
        s_res[o*33+n] = g_zp[ga] - s_res[o*33+n];
    }
    __syncthreads();
    for (int idx = tid; idx < D_*32; idx += 512) {
        int n = idx >> 10, o = idx & 1023;
        float v = s_res[o*33+n];
        __nv_bfloat16 h = __float2bfloat16(v);
        size_t a = ((size_t)s_bi[n]*T_ + s_ti[n])*D_ + o;
        g_qTH[a] = h;
        g_qTL[a] = __float2bfloat16(v - __bfloat162float(h));
    }
}

extern "C" void kernel_launch(void* const* d_in, const int* in_sizes, int n_in,
                              void* d_out, int out_size) {
    const float* z          = (const float*)d_in[0];
    const int*   lens       = (const int*)d_in[1];
    const float* in_proj_v  = (const float*)d_in[2];
    const float* in_proj_g  = (const float*)d_in[3];
    const float* in_proj_b  = (const float*)d_in[4];
    const float* out_proj_v = (const float*)d_in[5];
    const float* out_proj_g = (const float*)d_in[6];
    const float* out_proj_b = (const float*)d_in[7];
    const float* q_in_v     = (const float*)d_in[8];
    const float* q_in_g     = (const float*)d_in[9];
    const float* q_in_b     = (const float*)d_in[10];
    const float* q_out_v    = (const float*)d_in[11];
    const float* q_out_g    = (const float*)d_in[12];
    const float* q_out_b    = (const float*)d_in[13];
    const float* codebooks  = (const float*)d_in[14];
    float* dout = (float*)d_out;

    void *pWinT, *pWoutH, *pWoutL, *pzp, *pqTH, *pqTL;
    cudaGetSymbolAddress(&pWinT,  g_WinT);
    cudaGetSymbolAddress(&pWoutH, g_WoutH);
    cudaGetSymbolAddress(&pWoutL, g_WoutL);
    cudaGetSymbolAddress(&pzp,    g_zp);
    cudaGetSymbolAddress(&pqTH,   g_qTH);
    cudaGetSymbolAddress(&pqTL,   g_qTL);

    cudaFuncSetAttribute(rvq_scan,   cudaFuncAttributeMaxDynamicSharedMemorySize, 218656);
    cudaFuncSetAttribute(gemm_bf16x2, cudaFuncAttributeMaxDynamicSharedMemorySize, 122880);
    cudaFuncSetAttribute(sgemm256,   cudaFuncAttributeMaxDynamicSharedMemorySize, 73728);

    // rvq_scan is the 4th launch -> profiled
    prep_all<<<4368, 32>>>(in_proj_v, in_proj_g, out_proj_v, out_proj_g,
                           q_in_v, q_in_g, q_out_v, q_out_g, codebooks);
    masked_sel<<<NQ_, 256>>>(q_in_b, codebooks);

    sgemm256<<<dim3((T_+255)/256, D_/128, B_), 256, 73728>>>(
        (const float*)pWinT, z, in_proj_b, (float*)pzp, lens,
        T_, DIN, D_, (size_t)DIN*T_, (size_t)D_*T_);

    rvq_scan<<<NCOL/32, 512, 218656>>>(lens, codebooks, q_in_b, q_out_b, dout);

    gemv_S<<<D_, 32>>>(out_proj_b);
    commit_fin<<<1, 512>>>(dout);

    gemm_bf16x2<<<dim3((T_+127)/128, D_/128, B_), 256, 122880>>>(
        (const __nv_bfloat16*)pWoutH, (const __nv_bfloat16*)pWoutL,
        (const __nv_bfloat16*)pqTH, (const __nv_bfloat16*)pqTL,
        out_proj_b, dout, lens, T_, D_, (size_t)T_*D_, (size_t)D_*T_);
}